// round 1
// baseline (speedup 1.0000x reference)
#include <cuda_runtime.h>
#include <cuda_pipeline.h>
#include <math.h>

// ---------------- problem dims ----------------
#define T_LEN   512
#define BSZ     8
#define M_TOT   (T_LEN * BSZ)      // 4096
#define OBS_DIM 256
#define D_IN    2048
#define NHEAD   16
#define NSTATE  64
#define PHEAD   128                 // D_IN / NHEAD
#define NUNITS  256
#define NACT    64

// ---------------- scratch (device globals; allocation-free) ----------------
__device__ float g_X[M_TOT * D_IN];            // 32 MB  relu(obs@W_in+b)
__device__ float g_Bm[M_TOT * NHEAD * NSTATE]; // 16 MB
__device__ float g_Cm[M_TOT * NHEAD * NSTATE]; // 16 MB
__device__ float g_dt[M_TOT * NHEAD];          // dt (softplus applied)
__device__ float g_dec[M_TOT * NHEAD];         // exp(-A*dt)
__device__ float g_Y[M_TOT * D_IN];            // 32 MB scan output
__device__ float g_Z[M_TOT * NUNITS];          // 4 MB relu(y@W_yo+b)

// ---------------- generic tiled fp32 GEMM: C = op(A[M,K] @ W[K,N] (+bias)) ----------
// BM=BN=128, BK=8, 256 threads, 8x8 micro-tile. Requires M%128==0, N%128==0, K%8==0.
template<bool RELU, bool BIAS>
__global__ __launch_bounds__(256, 3)
void gemm128(const float* __restrict__ A, const float* __restrict__ W,
             const float* __restrict__ bias, float* __restrict__ C,
             int M, int N, int K)
{
    __shared__ float As[8][128];
    __shared__ float Bs[8][128];

    const int tid = threadIdx.x;
    const int bm  = blockIdx.y * 128;
    const int bn  = blockIdx.x * 128;

    const int ty   = tid >> 4;        // 0..15
    const int tx   = tid & 15;        // 0..15
    const int row0 = ty * 8;
    const int col0 = tx * 8;

    const int aRow = tid >> 1;        // 0..127
    const int aCol = (tid & 1) * 4;   // 0 or 4
    const int bRow = tid >> 5;        // 0..7
    const int bCol = (tid & 31) * 4;  // 0..124

    const float* Aptr = A + (size_t)(bm + aRow) * K + aCol;
    const float* Wptr = W + (size_t)bRow * N + bn + bCol;

    float acc[8][8];
#pragma unroll
    for (int i = 0; i < 8; i++)
#pragma unroll
        for (int j = 0; j < 8; j++) acc[i][j] = 0.f;

    for (int k0 = 0; k0 < K; k0 += 8) {
        float4 av = *(const float4*)(Aptr + k0);
        float4 bv = *(const float4*)(Wptr + (size_t)k0 * N);
        __syncthreads();
        As[aCol + 0][aRow] = av.x;
        As[aCol + 1][aRow] = av.y;
        As[aCol + 2][aRow] = av.z;
        As[aCol + 3][aRow] = av.w;
        *(float4*)&Bs[bRow][bCol] = bv;
        __syncthreads();
#pragma unroll
        for (int kk = 0; kk < 8; kk++) {
            float4 a0 = *(const float4*)&As[kk][row0];
            float4 a1 = *(const float4*)&As[kk][row0 + 4];
            float4 b0 = *(const float4*)&Bs[kk][col0];
            float4 b1 = *(const float4*)&Bs[kk][col0 + 4];
            float ar[8] = {a0.x, a0.y, a0.z, a0.w, a1.x, a1.y, a1.z, a1.w};
            float br[8] = {b0.x, b0.y, b0.z, b0.w, b1.x, b1.y, b1.z, b1.w};
#pragma unroll
            for (int i = 0; i < 8; i++)
#pragma unroll
                for (int j = 0; j < 8; j++)
                    acc[i][j] = fmaf(ar[i], br[j], acc[i][j]);
        }
    }

    float bb[8];
#pragma unroll
    for (int j = 0; j < 8; j++) bb[j] = BIAS ? bias[bn + col0 + j] : 0.f;

#pragma unroll
    for (int i = 0; i < 8; i++) {
        float4 v0, v1;
        float r[8];
#pragma unroll
        for (int j = 0; j < 8; j++) {
            float v = acc[i][j] + bb[j];
            if (RELU) v = fmaxf(v, 0.f);
            r[j] = v;
        }
        v0 = make_float4(r[0], r[1], r[2], r[3]);
        v1 = make_float4(r[4], r[5], r[6], r[7]);
        float* cp = C + (size_t)(bm + row0 + i) * N + bn + col0;
        *(float4*)cp       = v0;
        *(float4*)(cp + 4) = v1;
    }
}

// ---------------- dt projection + softplus + decay ----------------
// dt_raw[m,h] = X[m,:] @ W_dt[:,h]; dt = softplus(dt_raw + dt_bias[h]);
// dec = exp(-exp(A_log[h]) * dt). One block handles 16 rows.
__global__ __launch_bounds__(256)
void dtdecay_kernel(const float* __restrict__ X, const float* __restrict__ W_dt,
                    const float* __restrict__ dt_bias, const float* __restrict__ A_log,
                    float* __restrict__ dts, float* __restrict__ decs)
{
    __shared__ float Xs[16][64];
    __shared__ float Ws[64][16];
    const int tid = threadIdx.x;
    const int m0  = blockIdx.x * 16;
    const int h   = tid & 15;
    const int mi  = tid >> 4;

    float acc = 0.f;
    for (int k0 = 0; k0 < D_IN; k0 += 64) {
        __syncthreads();
        // Xs: 16x64 = 256 float4
        *(float4*)&Xs[tid >> 4][(tid & 15) * 4] =
            *(const float4*)&X[(size_t)(m0 + (tid >> 4)) * D_IN + k0 + (tid & 15) * 4];
        // Ws: 64x16 = 256 float4
        *(float4*)&Ws[tid >> 2][(tid & 3) * 4] =
            *(const float4*)&W_dt[(size_t)(k0 + (tid >> 2)) * NHEAD + (tid & 3) * 4];
        __syncthreads();
#pragma unroll
        for (int k = 0; k < 64; k++)
            acc = fmaf(Xs[mi][k], Ws[k][h], acc);
    }
    const int m = m0 + mi;
    float v  = acc + dt_bias[h];
    float dt = (v > 20.f) ? v : log1pf(expf(v));
    float A  = expf(A_log[h]);
    dts[m * NHEAD + h]  = dt;
    decs[m * NHEAD + h] = expf(-A * dt);
}

// ---------------- selective scan ----------------
// 128 blocks = (b,h) pairs, 256 threads. Thread (p = tid&127, half = tid>>7)
// owns state h[p, half*32 .. half*32+31] in 32 registers. Double-buffered
// cp.async staging of x(128)/B(64)/C(64)/dt/dec per step.
__global__ __launch_bounds__(256, 1)
void scan_kernel(const float* __restrict__ X, const float* __restrict__ Bm,
                 const float* __restrict__ Cm, const float* __restrict__ dts,
                 const float* __restrict__ decs, float* __restrict__ Y)
{
    const int bh = blockIdx.x;
    const int b  = bh >> 4;
    const int h  = bh & 15;
    const int tid  = threadIdx.x;
    const int p    = tid & 127;
    const int half = tid >> 7;

    __shared__ float xb[2][PHEAD];
    __shared__ float Bb[2][NSTATE];
    __shared__ float Cb[2][NSTATE];
    __shared__ float sc[2][2];          // [par][0]=dt, [par][1]=dec
    __shared__ float yp[2][2][PHEAD];

    float hs[32];
#pragma unroll
    for (int i = 0; i < 32; i++) hs[i] = 0.f;

    // issue loads for timestep t into buffer par
    auto issue = [&](int t, int par) {
        const size_t m = (size_t)t * BSZ + b;
        if (tid < 128) {
            __pipeline_memcpy_async(&xb[par][p], X + m * D_IN + h * PHEAD + p, 4);
            if (tid == 0)
                __pipeline_memcpy_async(&sc[par][0], dts + m * NHEAD + h, 4);
            if (tid == 1)
                __pipeline_memcpy_async(&sc[par][1], decs + m * NHEAD + h, 4);
        } else if (tid < 192) {
            __pipeline_memcpy_async(&Bb[par][tid - 128],
                                    Bm + m * (NHEAD * NSTATE) + h * NSTATE + (tid - 128), 4);
        } else {
            __pipeline_memcpy_async(&Cb[par][tid - 192],
                                    Cm + m * (NHEAD * NSTATE) + h * NSTATE + (tid - 192), 4);
        }
    };

    issue(0, 0);
    __pipeline_commit();
    __pipeline_wait_prior(0);
    __syncthreads();

    for (int t = 0; t < T_LEN; t++) {
        const int par = t & 1;
        if (t + 1 < T_LEN) issue(t + 1, par ^ 1);
        __pipeline_commit();

        const float dtv = sc[par][0];
        const float dec = sc[par][1];
        const float xp  = xb[par][p];
        const float c   = dtv * xp;

        const float4* B4 = (const float4*)&Bb[par][half * 32];
        const float4* C4 = (const float4*)&Cb[par][half * 32];
        float y0 = 0.f, y1 = 0.f, y2 = 0.f, y3 = 0.f;
#pragma unroll
        for (int j = 0; j < 8; j++) {
            float4 bv = B4[j];
            float4 cv = C4[j];
            hs[4*j+0] = fmaf(dec, hs[4*j+0], c * bv.x); y0 = fmaf(hs[4*j+0], cv.x, y0);
            hs[4*j+1] = fmaf(dec, hs[4*j+1], c * bv.y); y1 = fmaf(hs[4*j+1], cv.y, y1);
            hs[4*j+2] = fmaf(dec, hs[4*j+2], c * bv.z); y2 = fmaf(hs[4*j+2], cv.z, y2);
            hs[4*j+3] = fmaf(dec, hs[4*j+3], c * bv.w); y3 = fmaf(hs[4*j+3], cv.w, y3);
        }
        yp[par][half][p] = (y0 + y1) + (y2 + y3);

        __pipeline_wait_prior(0);
        __syncthreads();

        if (tid < 128) {
            const size_t m = (size_t)t * BSZ + b;
            Y[m * D_IN + h * PHEAD + p] = yp[par][0][p] + yp[par][1][p];
        }
    }
}

// ---------------- policy head: out[m,64] = Z[m,256] @ W_head + b_head ----------------
__global__ __launch_bounds__(256)
void head_kernel(const float* __restrict__ Z, const float* __restrict__ Wh,
                 const float* __restrict__ bh, float* __restrict__ out)
{
    __shared__ float Zs[4][NUNITS];
    __shared__ float Ws[64][NACT];
    const int tid = threadIdx.x;
    const int m0  = blockIdx.x * 4;
    const int n   = tid & 63;
    const int mi  = tid >> 6;

    // load 4 rows of Z: 4*256 = 256 float4
    *(float4*)&Zs[tid >> 6][(tid & 63) * 4] =
        *(const float4*)&Z[(size_t)(m0 + (tid >> 6)) * NUNITS + (tid & 63) * 4];

    float acc = bh[n];
    for (int k0 = 0; k0 < NUNITS; k0 += 64) {
        __syncthreads();
        // load 64x64 chunk of W_head: 1024 float4, 4 per thread
#pragma unroll
        for (int j = 0; j < 4; j++) {
            int idx = tid + j * 256;
            int r = idx >> 4, c4 = (idx & 15) * 4;
            *(float4*)&Ws[r][c4] = *(const float4*)&Wh[(size_t)(k0 + r) * NACT + c4];
        }
        __syncthreads();
#pragma unroll
        for (int k = 0; k < 64; k++)
            acc = fmaf(Zs[mi][k0 + k], Ws[k][n], acc);
    }
    out[(size_t)(m0 + mi) * NACT + n] = acc;
}

// ---------------- launch ----------------
extern "C" void kernel_launch(void* const* d_in, const int* in_sizes, int n_in,
                              void* d_out, int out_size)
{
    const float* obs     = (const float*)d_in[0];
    const float* W_in    = (const float*)d_in[1];
    const float* b_in    = (const float*)d_in[2];
    const float* A_log   = (const float*)d_in[3];
    const float* dt_bias = (const float*)d_in[4];
    const float* W_dt    = (const float*)d_in[5];
    const float* W_B     = (const float*)d_in[6];
    const float* W_C     = (const float*)d_in[7];
    const float* W_yo    = (const float*)d_in[8];
    const float* b_yo    = (const float*)d_in[9];
    const float* W_head  = (const float*)d_in[10];
    const float* b_head  = (const float*)d_in[11];
    float* out = (float*)d_out;

    float *X, *Bm, *Cm, *dts, *dec, *Y, *Z;
    cudaGetSymbolAddress((void**)&X,   g_X);
    cudaGetSymbolAddress((void**)&Bm,  g_Bm);
    cudaGetSymbolAddress((void**)&Cm,  g_Cm);
    cudaGetSymbolAddress((void**)&dts, g_dt);
    cudaGetSymbolAddress((void**)&dec, g_dec);
    cudaGetSymbolAddress((void**)&Y,   g_Y);
    cudaGetSymbolAddress((void**)&Z,   g_Z);

    // 1) X = relu(obs @ W_in + b_in)   [4096 x 2048, K=256]
    gemm128<true, true><<<dim3(D_IN / 128, M_TOT / 128), 256>>>(
        obs, W_in, b_in, X, M_TOT, D_IN, OBS_DIM);

    // 2) dt / decay precompute  [4096 x 16, K=2048]
    dtdecay_kernel<<<M_TOT / 16, 256>>>(X, W_dt, dt_bias, A_log, dts, dec);

    // 3) B = X @ W_B, C = X @ W_C  [4096 x 1024, K=2048]
    gemm128<false, false><<<dim3((NHEAD * NSTATE) / 128, M_TOT / 128), 256>>>(
        X, W_B, nullptr, Bm, M_TOT, NHEAD * NSTATE, D_IN);
    gemm128<false, false><<<dim3((NHEAD * NSTATE) / 128, M_TOT / 128), 256>>>(
        X, W_C, nullptr, Cm, M_TOT, NHEAD * NSTATE, D_IN);

    // 4) selective scan -> Y
    scan_kernel<<<BSZ * NHEAD, 256>>>(X, Bm, Cm, dts, dec, Y);

    // 5) Z = relu(Y @ W_yo + b_yo)  [4096 x 256, K=2048]
    gemm128<true, true><<<dim3(NUNITS / 128, M_TOT / 128), 256>>>(
        Y, W_yo, b_yo, Z, M_TOT, NUNITS, D_IN);

    // 6) logits = Z @ W_head + b_head  [4096 x 64, K=256]
    head_kernel<<<M_TOT / 4, 256>>>(Z, W_head, b_head, out);
}

// round 3
// speedup vs baseline: 3.9104x; 3.9104x over previous
#include <cuda_runtime.h>
#include <cuda_pipeline.h>
#include <cuda_bf16.h>
#include <math.h>
#include <stdint.h>

// ---------------- problem dims ----------------
#define T_LEN   512
#define BSZ     8
#define M_TOT   (T_LEN * BSZ)      // 4096
#define OBS_DIM 256
#define D_IN    2048
#define NHEAD   16
#define NSTATE  64
#define PHEAD   128                 // D_IN / NHEAD
#define NUNITS  256
#define NACT    64
#define HN      (NHEAD * NSTATE)    // 1024

// ---------------- scratch (device globals; allocation-free) ----------------
__device__ float          g_X   [M_TOT * D_IN];
__device__ __nv_bfloat16  g_Xhi [M_TOT * D_IN];
__device__ __nv_bfloat16  g_Xlo [M_TOT * D_IN];
__device__ float          g_Bm  [M_TOT * HN];
__device__ float          g_Cm  [M_TOT * HN];
__device__ float          g_dt  [M_TOT * NHEAD];
__device__ float          g_dec [M_TOT * NHEAD];
__device__ __nv_bfloat16  g_Yhi [M_TOT * D_IN];
__device__ __nv_bfloat16  g_Ylo [M_TOT * D_IN];
__device__ float          g_Z   [M_TOT * NUNITS];
__device__ __nv_bfloat16  g_obs_hi[M_TOT * OBS_DIM];
__device__ __nv_bfloat16  g_obs_lo[M_TOT * OBS_DIM];
__device__ __nv_bfloat16  g_Win_hi[D_IN * OBS_DIM];   // [N,K]
__device__ __nv_bfloat16  g_Win_lo[D_IN * OBS_DIM];
__device__ __nv_bfloat16  g_WB_hi [HN * D_IN];
__device__ __nv_bfloat16  g_WB_lo [HN * D_IN];
__device__ __nv_bfloat16  g_WC_hi [HN * D_IN];
__device__ __nv_bfloat16  g_WC_lo [HN * D_IN];
__device__ __nv_bfloat16  g_Wyo_hi[NUNITS * D_IN];
__device__ __nv_bfloat16  g_Wyo_lo[NUNITS * D_IN];

// ---------------- low-level helpers (all legal on base sm_103 target) -------
__device__ __forceinline__ uint32_t smem_u32(const void* p) {
    uint32_t a;
    asm("{ .reg .u64 t; cvta.to.shared.u64 t, %1; cvt.u32.u64 %0, t; }" : "=r"(a) : "l"(p));
    return a;
}
__device__ __forceinline__ void ldsm_x4(uint32_t* r, uint32_t addr) {
    asm volatile("ldmatrix.sync.aligned.m8n8.x4.shared.b16 {%0,%1,%2,%3}, [%4];"
                 : "=r"(r[0]), "=r"(r[1]), "=r"(r[2]), "=r"(r[3]) : "r"(addr));
}
__device__ __forceinline__ void ldsm_x2(uint32_t* r, uint32_t addr) {
    asm volatile("ldmatrix.sync.aligned.m8n8.x2.shared.b16 {%0,%1}, [%2];"
                 : "=r"(r[0]), "=r"(r[1]) : "r"(addr));
}
__device__ __forceinline__ void mma_bf16(float* c, const uint32_t* a, const uint32_t* b) {
    asm volatile("mma.sync.aligned.m16n8k16.row.col.f32.bf16.bf16.f32 "
                 "{%0,%1,%2,%3}, {%4,%5,%6,%7}, {%8,%9}, {%0,%1,%2,%3};"
                 : "+f"(c[0]), "+f"(c[1]), "+f"(c[2]), "+f"(c[3])
                 : "r"(a[0]), "r"(a[1]), "r"(a[2]), "r"(a[3]), "r"(b[0]), "r"(b[1]));
}

// ---------------- conversion kernels ----------------
__global__ void rowconv_kernel(const float* __restrict__ src,
                               __nv_bfloat16* __restrict__ hi,
                               __nv_bfloat16* __restrict__ lo, int n)
{
    int i = blockIdx.x * blockDim.x + threadIdx.x;
    if (i * 4 >= n) return;
    float4 v = *(const float4*)(src + i * 4);
    float vv[4] = {v.x, v.y, v.z, v.w};
#pragma unroll
    for (int j = 0; j < 4; j++) {
        __nv_bfloat16 h = __float2bfloat16(vv[j]);
        hi[i * 4 + j] = h;
        lo[i * 4 + j] = __float2bfloat16(vv[j] - __bfloat162float(h));
    }
}

// W [K,N] fp32 -> T [N,K] bf16 hi/lo (transpose + split)
__global__ void transconv_kernel(const float* __restrict__ W,
                                 __nv_bfloat16* __restrict__ Thi,
                                 __nv_bfloat16* __restrict__ Tlo, int K, int N)
{
    __shared__ float s[32][33];
    int tx = threadIdx.x, ty = threadIdx.y;
    int n0 = blockIdx.x * 32, k0 = blockIdx.y * 32;
#pragma unroll
    for (int i = 0; i < 4; i++)
        s[ty + i * 8][tx] = W[(size_t)(k0 + ty + i * 8) * N + n0 + tx];
    __syncthreads();
#pragma unroll
    for (int i = 0; i < 4; i++) {
        int n = n0 + ty + i * 8, k = k0 + tx;
        float v = s[tx][ty + i * 8];
        __nv_bfloat16 h = __float2bfloat16(v);
        Thi[(size_t)n * K + k] = h;
        Tlo[(size_t)n * K + k] = __float2bfloat16(v - __bfloat162float(h));
    }
}

// ---------------- mma.sync split-bf16 GEMM ----------------
// C[M,N] = (Ahi+Alo)[M,K] @ (Bhi+Blo)[N,K]^T, dropping lo*lo.
// 128x128 block tile, BK=32, 8 warps (2x4), warp tile 64x32.
// smem per buffer: 4 tiles (Ahi,Alo,Bhi,Blo), each 128 rows x 80 bytes.
#define ROWB      80                       // padded row stride (bytes)
#define TILE_B    (128 * ROWB)             // 10240
#define BUF_B     (4 * TILE_B)             // 40960
#define GEMM_SMEM (2 * BUF_B)              // 81920

template<int KCHUNKS, bool RELU, bool BIAS, bool HILO>
__global__ __launch_bounds__(256, 1)
void mma_gemm(const __nv_bfloat16* __restrict__ Ahi, const __nv_bfloat16* __restrict__ Alo,
              const __nv_bfloat16* __restrict__ Bhi, const __nv_bfloat16* __restrict__ Blo,
              const float* __restrict__ bias,
              float* __restrict__ Cout,
              __nv_bfloat16* __restrict__ Chi, __nv_bfloat16* __restrict__ Clo,
              int M, int N, int K)
{
    extern __shared__ char smem[];
    const uint32_t sbase = smem_u32(smem);
    const int tid  = threadIdx.x;
    const int lane = tid & 31, wid = tid >> 5;
    const int warp_m = wid >> 2;          // 0..1
    const int warp_n = wid & 3;           // 0..3
    const int bn = blockIdx.x * 128;
    const int bm = blockIdx.y * 128;

    const __nv_bfloat16* srcs[4] = {Ahi, Alo, Bhi, Blo};

    auto load_chunk = [&](int c, int buf) {
#pragma unroll
        for (int w = 0; w < 4; w++) {
            const int rowbase = (w < 2) ? bm : bn;
            const __nv_bfloat16* src = srcs[w];
#pragma unroll
            for (int t = 0; t < 2; t++) {
                int idx = tid + t * 256;          // 0..511
                int row = idx >> 2, seg = idx & 3;
                char* dst = smem + buf * BUF_B + w * TILE_B + row * ROWB + seg * 16;
                const char* s = (const char*)src +
                    ((size_t)(rowbase + row) * K + (size_t)c * 32) * 2 + seg * 16;
                __pipeline_memcpy_async(dst, s, 16);
            }
        }
    };

    float acc[4][4][4];
#pragma unroll
    for (int i = 0; i < 4; i++)
#pragma unroll
        for (int j = 0; j < 4; j++)
#pragma unroll
            for (int q = 0; q < 4; q++) acc[i][j][q] = 0.f;

    load_chunk(0, 0);
    __pipeline_commit();
    __pipeline_wait_prior(0);
    __syncthreads();

    const uint32_t a_lane_off = (uint32_t)((lane & 15) * ROWB + (lane >> 4) * 16);
    const uint32_t b_lane_off = (uint32_t)((lane & 7) * ROWB + ((lane >> 3) & 1) * 16);

    for (int c = 0; c < KCHUNKS; c++) {
        if (c + 1 < KCHUNKS) { load_chunk(c + 1, (c + 1) & 1); __pipeline_commit(); }

        const uint32_t bufb = sbase + (c & 1) * BUF_B;
#pragma unroll
        for (int s = 0; s < 2; s++) {
            uint32_t ah[4][4], al[4][4], bh[4][2], bl[4][2];
            const uint32_t ks = s * 32;   // byte offset of k-step
#pragma unroll
            for (int i = 0; i < 4; i++) {
                uint32_t ro = (uint32_t)((warp_m * 64 + i * 16) * ROWB) + ks + a_lane_off;
                ldsm_x4(ah[i], bufb + 0 * TILE_B + ro);
                ldsm_x4(al[i], bufb + 1 * TILE_B + ro);
            }
#pragma unroll
            for (int j = 0; j < 4; j++) {
                uint32_t ro = (uint32_t)((warp_n * 32 + j * 8) * ROWB) + ks + b_lane_off;
                ldsm_x2(bh[j], bufb + 2 * TILE_B + ro);
                ldsm_x2(bl[j], bufb + 3 * TILE_B + ro);
            }
#pragma unroll
            for (int i = 0; i < 4; i++)
#pragma unroll
                for (int j = 0; j < 4; j++) {
                    mma_bf16(acc[i][j], ah[i], bh[j]);
                    mma_bf16(acc[i][j], ah[i], bl[j]);
                    mma_bf16(acc[i][j], al[i], bh[j]);
                }
        }
        if (c + 1 < KCHUNKS) __pipeline_wait_prior(0);
        __syncthreads();
    }

    // epilogue
    const int r0 = lane >> 2;
    const int q0 = (lane & 3) * 2;
#pragma unroll
    for (int j = 0; j < 4; j++) {
        const int n0 = bn + warp_n * 32 + j * 8 + q0;
        float b0 = BIAS ? bias[n0] : 0.f;
        float b1 = BIAS ? bias[n0 + 1] : 0.f;
#pragma unroll
        for (int i = 0; i < 4; i++) {
            const int m0 = bm + warp_m * 64 + i * 16 + r0;
            float v0 = acc[i][j][0] + b0, v1 = acc[i][j][1] + b1;
            float v2 = acc[i][j][2] + b0, v3 = acc[i][j][3] + b1;
            if (RELU) { v0 = fmaxf(v0, 0.f); v1 = fmaxf(v1, 0.f);
                        v2 = fmaxf(v2, 0.f); v3 = fmaxf(v3, 0.f); }
            *(float2*)&Cout[(size_t)m0 * N + n0]       = make_float2(v0, v1);
            *(float2*)&Cout[(size_t)(m0 + 8) * N + n0] = make_float2(v2, v3);
            if (HILO) {
                __nv_bfloat16 h0 = __float2bfloat16(v0), h1 = __float2bfloat16(v1);
                __nv_bfloat16 h2 = __float2bfloat16(v2), h3 = __float2bfloat16(v3);
                __nv_bfloat162 hp0 = {h0, h1}, hp1 = {h2, h3};
                __nv_bfloat162 lp0 = {__float2bfloat16(v0 - __bfloat162float(h0)),
                                      __float2bfloat16(v1 - __bfloat162float(h1))};
                __nv_bfloat162 lp1 = {__float2bfloat16(v2 - __bfloat162float(h2)),
                                      __float2bfloat16(v3 - __bfloat162float(h3))};
                *(__nv_bfloat162*)&Chi[(size_t)m0 * N + n0]       = hp0;
                *(__nv_bfloat162*)&Chi[(size_t)(m0 + 8) * N + n0] = hp1;
                *(__nv_bfloat162*)&Clo[(size_t)m0 * N + n0]       = lp0;
                *(__nv_bfloat162*)&Clo[(size_t)(m0 + 8) * N + n0] = lp1;
            }
        }
    }
}

// ---------------- dt projection + softplus + decay ----------------
__global__ __launch_bounds__(256)
void dtdecay_kernel(const float* __restrict__ X, const float* __restrict__ W_dt,
                    const float* __restrict__ dt_bias, const float* __restrict__ A_log,
                    float* __restrict__ dts, float* __restrict__ decs)
{
    __shared__ float Xs[16][64];
    __shared__ float Ws[64][16];
    const int tid = threadIdx.x;
    const int m0  = blockIdx.x * 16;
    const int h   = tid & 15;
    const int mi  = tid >> 4;

    float acc = 0.f;
    for (int k0 = 0; k0 < D_IN; k0 += 64) {
        __syncthreads();
        *(float4*)&Xs[tid >> 4][(tid & 15) * 4] =
            *(const float4*)&X[(size_t)(m0 + (tid >> 4)) * D_IN + k0 + (tid & 15) * 4];
        *(float4*)&Ws[tid >> 2][(tid & 3) * 4] =
            *(const float4*)&W_dt[(size_t)(k0 + (tid >> 2)) * NHEAD + (tid & 3) * 4];
        __syncthreads();
#pragma unroll
        for (int k = 0; k < 64; k++)
            acc = fmaf(Xs[mi][k], Ws[k][h], acc);
    }
    const int m = m0 + mi;
    float v  = acc + dt_bias[h];
    float dt = (v > 20.f) ? v : log1pf(expf(v));
    float A  = expf(A_log[h]);
    dts[m * NHEAD + h]  = dt;
    decs[m * NHEAD + h] = expf(-A * dt);
}

// ---------------- selective scan ----------------
__global__ __launch_bounds__(128, 1)
void scan_kernel(const float* __restrict__ X, const float* __restrict__ Bm,
                 const float* __restrict__ Cm, const float* __restrict__ dts,
                 const float* __restrict__ decs,
                 __nv_bfloat16* __restrict__ Yhi, __nv_bfloat16* __restrict__ Ylo)
{
    const int bh = blockIdx.x;
    const int b  = bh >> 4;
    const int h  = bh & 15;
    const int tid = threadIdx.x;

    __shared__ float xb[4][PHEAD];
    __shared__ float Bb[4][NSTATE];
    __shared__ float Cb[4][NSTATE];
    __shared__ float sc[4][2];

    float hs[64];
#pragma unroll
    for (int i = 0; i < 64; i++) hs[i] = 0.f;

    auto issue = [&](int t) {
        const int st = t & 3;
        const size_t m = (size_t)t * BSZ + b;
        __pipeline_memcpy_async(&xb[st][tid], X + m * D_IN + h * PHEAD + tid, 4);
        if (tid < 64)
            __pipeline_memcpy_async(&Bb[st][tid], Bm + m * HN + h * NSTATE + tid, 4);
        else
            __pipeline_memcpy_async(&Cb[st][tid - 64], Cm + m * HN + h * NSTATE + (tid - 64), 4);
        if (tid == 0) __pipeline_memcpy_async(&sc[st][0], dts  + m * NHEAD + h, 4);
        if (tid == 1) __pipeline_memcpy_async(&sc[st][1], decs + m * NHEAD + h, 4);
    };

    issue(0); __pipeline_commit();
    issue(1); __pipeline_commit();
    issue(2); __pipeline_commit();

    for (int t = 0; t < T_LEN; t++) {
        const int st = t & 3;
        __pipeline_wait_prior(2);
        __syncthreads();
        if (t + 3 < T_LEN) issue(t + 3);
        __pipeline_commit();

        const float dtv = sc[st][0];
        const float dec = sc[st][1];
        const float cc  = dtv * xb[st][tid];

        const float4* B4 = (const float4*)Bb[st];
        const float4* C4 = (const float4*)Cb[st];
        float y0 = 0.f, y1 = 0.f, y2 = 0.f, y3 = 0.f;
#pragma unroll
        for (int j = 0; j < 16; j++) {
            float4 bv = B4[j];
            float4 cv = C4[j];
            hs[4*j+0] = fmaf(dec, hs[4*j+0], cc * bv.x); y0 = fmaf(hs[4*j+0], cv.x, y0);
            hs[4*j+1] = fmaf(dec, hs[4*j+1], cc * bv.y); y1 = fmaf(hs[4*j+1], cv.y, y1);
            hs[4*j+2] = fmaf(dec, hs[4*j+2], cc * bv.z); y2 = fmaf(hs[4*j+2], cv.z, y2);
            hs[4*j+3] = fmaf(dec, hs[4*j+3], cc * bv.w); y3 = fmaf(hs[4*j+3], cv.w, y3);
        }
        const float y = (y0 + y1) + (y2 + y3);
        const size_t m = (size_t)t * BSZ + b;
        __nv_bfloat16 hy = __float2bfloat16(y);
        Yhi[m * D_IN + h * PHEAD + tid] = hy;
        Ylo[m * D_IN + h * PHEAD + tid] = __float2bfloat16(y - __bfloat162float(hy));
    }
}

// ---------------- policy head ----------------
__global__ __launch_bounds__(256)
void head_kernel(const float* __restrict__ Z, const float* __restrict__ Wh,
                 const float* __restrict__ bh, float* __restrict__ out)
{
    __shared__ float Zs[4][NUNITS];
    __shared__ float Ws[64][NACT];
    const int tid = threadIdx.x;
    const int m0  = blockIdx.x * 4;
    const int n   = tid & 63;
    const int mi  = tid >> 6;

    *(float4*)&Zs[tid >> 6][(tid & 63) * 4] =
        *(const float4*)&Z[(size_t)(m0 + (tid >> 6)) * NUNITS + (tid & 63) * 4];

    float acc = bh[n];
    for (int k0 = 0; k0 < NUNITS; k0 += 64) {
        __syncthreads();
#pragma unroll
        for (int j = 0; j < 4; j++) {
            int idx = tid + j * 256;
            int r = idx >> 4, c4 = (idx & 15) * 4;
            *(float4*)&Ws[r][c4] = *(const float4*)&Wh[(size_t)(k0 + r) * NACT + c4];
        }
        __syncthreads();
#pragma unroll
        for (int k = 0; k < 64; k++)
            acc = fmaf(Zs[mi][k0 + k], Ws[k][n], acc);
    }
    out[(size_t)(m0 + mi) * NACT + n] = acc;
}

// ---------------- launch ----------------
extern "C" void kernel_launch(void* const* d_in, const int* in_sizes, int n_in,
                              void* d_out, int out_size)
{
    const float* obs     = (const float*)d_in[0];
    const float* W_in    = (const float*)d_in[1];
    const float* b_in    = (const float*)d_in[2];
    const float* A_log   = (const float*)d_in[3];
    const float* dt_bias = (const float*)d_in[4];
    const float* W_dt    = (const float*)d_in[5];
    const float* W_B     = (const float*)d_in[6];
    const float* W_C     = (const float*)d_in[7];
    const float* W_yo    = (const float*)d_in[8];
    const float* b_yo    = (const float*)d_in[9];
    const float* W_head  = (const float*)d_in[10];
    const float* b_head  = (const float*)d_in[11];
    float* out = (float*)d_out;

    float *X, *Bmp, *Cmp, *dts, *dec, *Z;
    __nv_bfloat16 *Xhi, *Xlo, *Yhi, *Ylo, *obsh, *obsl;
    __nv_bfloat16 *Winh, *Winl, *WBh, *WBl, *WCh, *WCl, *Wyoh, *Wyol;
    cudaGetSymbolAddress((void**)&X,    g_X);
    cudaGetSymbolAddress((void**)&Xhi,  g_Xhi);
    cudaGetSymbolAddress((void**)&Xlo,  g_Xlo);
    cudaGetSymbolAddress((void**)&Bmp,  g_Bm);
    cudaGetSymbolAddress((void**)&Cmp,  g_Cm);
    cudaGetSymbolAddress((void**)&dts,  g_dt);
    cudaGetSymbolAddress((void**)&dec,  g_dec);
    cudaGetSymbolAddress((void**)&Yhi,  g_Yhi);
    cudaGetSymbolAddress((void**)&Ylo,  g_Ylo);
    cudaGetSymbolAddress((void**)&Z,    g_Z);
    cudaGetSymbolAddress((void**)&obsh, g_obs_hi);
    cudaGetSymbolAddress((void**)&obsl, g_obs_lo);
    cudaGetSymbolAddress((void**)&Winh, g_Win_hi);
    cudaGetSymbolAddress((void**)&Winl, g_Win_lo);
    cudaGetSymbolAddress((void**)&WBh,  g_WB_hi);
    cudaGetSymbolAddress((void**)&WBl,  g_WB_lo);
    cudaGetSymbolAddress((void**)&WCh,  g_WC_hi);
    cudaGetSymbolAddress((void**)&WCl,  g_WC_lo);
    cudaGetSymbolAddress((void**)&Wyoh, g_Wyo_hi);
    cudaGetSymbolAddress((void**)&Wyol, g_Wyo_lo);

    cudaFuncSetAttribute(mma_gemm<8,  true,  true,  true >, cudaFuncAttributeMaxDynamicSharedMemorySize, GEMM_SMEM);
    cudaFuncSetAttribute(mma_gemm<64, false, false, false>, cudaFuncAttributeMaxDynamicSharedMemorySize, GEMM_SMEM);
    cudaFuncSetAttribute(mma_gemm<64, true,  true,  false>, cudaFuncAttributeMaxDynamicSharedMemorySize, GEMM_SMEM);

    // 0) operand conversions
    rowconv_kernel<<<(M_TOT * OBS_DIM / 4 + 255) / 256, 256>>>(obs, obsh, obsl, M_TOT * OBS_DIM);
    transconv_kernel<<<dim3(D_IN / 32, OBS_DIM / 32), dim3(32, 8)>>>(W_in, Winh, Winl, OBS_DIM, D_IN);
    transconv_kernel<<<dim3(HN / 32,  D_IN / 32),   dim3(32, 8)>>>(W_B,  WBh,  WBl,  D_IN, HN);
    transconv_kernel<<<dim3(HN / 32,  D_IN / 32),   dim3(32, 8)>>>(W_C,  WCh,  WCl,  D_IN, HN);
    transconv_kernel<<<dim3(NUNITS / 32, D_IN / 32), dim3(32, 8)>>>(W_yo, Wyoh, Wyol, D_IN, NUNITS);

    // 1) X = relu(obs @ W_in + b_in)  [4096 x 2048, K=256]  (+ hi/lo split)
    mma_gemm<8, true, true, true><<<dim3(D_IN / 128, M_TOT / 128), 256, GEMM_SMEM>>>(
        obsh, obsl, Winh, Winl, b_in, X, Xhi, Xlo, M_TOT, D_IN, OBS_DIM);

    // 2) dt / decay
    dtdecay_kernel<<<M_TOT / 16, 256>>>(X, W_dt, dt_bias, A_log, dts, dec);

    // 3) B = X @ W_B, C = X @ W_C  [4096 x 1024, K=2048]
    mma_gemm<64, false, false, false><<<dim3(HN / 128, M_TOT / 128), 256, GEMM_SMEM>>>(
        Xhi, Xlo, WBh, WBl, nullptr, Bmp, nullptr, nullptr, M_TOT, HN, D_IN);
    mma_gemm<64, false, false, false><<<dim3(HN / 128, M_TOT / 128), 256, GEMM_SMEM>>>(
        Xhi, Xlo, WCh, WCl, nullptr, Cmp, nullptr, nullptr, M_TOT, HN, D_IN);

    // 4) selective scan -> Y (hi/lo)
    scan_kernel<<<BSZ * NHEAD, 128>>>(X, Bmp, Cmp, dts, dec, Yhi, Ylo);

    // 5) Z = relu(Y @ W_yo + b_yo)  [4096 x 256, K=2048]
    mma_gemm<64, true, true, false><<<dim3(NUNITS / 128, M_TOT / 128), 256, GEMM_SMEM>>>(
        Yhi, Ylo, Wyoh, Wyol, b_yo, Z, nullptr, nullptr, M_TOT, NUNITS, D_IN);

    // 6) logits = Z @ W_head + b_head
    head_kernel<<<M_TOT / 4, 256>>>(Z, W_head, b_head, out);
}

// round 4
// speedup vs baseline: 4.2160x; 1.0781x over previous
#include <cuda_runtime.h>
#include <cuda_pipeline.h>
#include <cuda_bf16.h>
#include <math.h>
#include <stdint.h>

// ---------------- problem dims ----------------
#define T_LEN   512
#define BSZ     8
#define M_TOT   (T_LEN * BSZ)      // 4096
#define OBS_DIM 256
#define D_IN    2048
#define NHEAD   16
#define NSTATE  64
#define PHEAD   128                 // D_IN / NHEAD
#define NUNITS  256
#define NACT    64
#define HN      (NHEAD * NSTATE)    // 1024

// ---------------- scratch (device globals; allocation-free) ----------------
__device__ float          g_X   [M_TOT * D_IN];
__device__ __nv_bfloat16  g_Xhi [M_TOT * D_IN];
__device__ __nv_bfloat16  g_Xlo [M_TOT * D_IN];
__device__ float          g_Bm  [M_TOT * HN];
__device__ float          g_Cm  [M_TOT * HN];
__device__ float          g_dt  [M_TOT * NHEAD];
__device__ float          g_dec [M_TOT * NHEAD];
__device__ __nv_bfloat16  g_Yhi [M_TOT * D_IN];
__device__ __nv_bfloat16  g_Ylo [M_TOT * D_IN];
__device__ float          g_Z   [M_TOT * NUNITS];
__device__ __nv_bfloat16  g_obs_hi[M_TOT * OBS_DIM];
__device__ __nv_bfloat16  g_obs_lo[M_TOT * OBS_DIM];
__device__ __nv_bfloat16  g_Win_hi[D_IN * OBS_DIM];   // [N,K]
__device__ __nv_bfloat16  g_Win_lo[D_IN * OBS_DIM];
__device__ __nv_bfloat16  g_WB_hi [HN * D_IN];
__device__ __nv_bfloat16  g_WB_lo [HN * D_IN];
__device__ __nv_bfloat16  g_WC_hi [HN * D_IN];
__device__ __nv_bfloat16  g_WC_lo [HN * D_IN];
__device__ __nv_bfloat16  g_Wyo_hi[NUNITS * D_IN];
__device__ __nv_bfloat16  g_Wyo_lo[NUNITS * D_IN];

// ---------------- low-level helpers (base sm_103 target legal) -------------
__device__ __forceinline__ uint32_t smem_u32(const void* p) {
    uint32_t a;
    asm("{ .reg .u64 t; cvta.to.shared.u64 t, %1; cvt.u32.u64 %0, t; }" : "=r"(a) : "l"(p));
    return a;
}
__device__ __forceinline__ void ldsm_x4(uint32_t* r, uint32_t addr) {
    asm volatile("ldmatrix.sync.aligned.m8n8.x4.shared.b16 {%0,%1,%2,%3}, [%4];"
                 : "=r"(r[0]), "=r"(r[1]), "=r"(r[2]), "=r"(r[3]) : "r"(addr));
}
__device__ __forceinline__ void ldsm_x2(uint32_t* r, uint32_t addr) {
    asm volatile("ldmatrix.sync.aligned.m8n8.x2.shared.b16 {%0,%1}, [%2];"
                 : "=r"(r[0]), "=r"(r[1]) : "r"(addr));
}
__device__ __forceinline__ void mma_bf16(float* c, const uint32_t* a, const uint32_t* b) {
    asm volatile("mma.sync.aligned.m16n8k16.row.col.f32.bf16.bf16.f32 "
                 "{%0,%1,%2,%3}, {%4,%5,%6,%7}, {%8,%9}, {%0,%1,%2,%3};"
                 : "+f"(c[0]), "+f"(c[1]), "+f"(c[2]), "+f"(c[3])
                 : "r"(a[0]), "r"(a[1]), "r"(a[2]), "r"(a[3]), "r"(b[0]), "r"(b[1]));
}
// packed f32x2 (PTX 8.6, sm_100+ base ISA -> SASS FFMA2)
typedef unsigned long long ull;
__device__ __forceinline__ ull pk2(float lo, float hi) {
    ull r; asm("mov.b64 %0, {%1, %2};" : "=l"(r) : "f"(lo), "f"(hi)); return r;
}
__device__ __forceinline__ void upk2(float& lo, float& hi, ull v) {
    asm("mov.b64 {%0, %1}, %2;" : "=f"(lo), "=f"(hi) : "l"(v));
}
__device__ __forceinline__ ull fma2(ull a, ull b, ull c) {
    ull d; asm("fma.rn.f32x2 %0, %1, %2, %3;" : "=l"(d) : "l"(a), "l"(b), "l"(c)); return d;
}
__device__ __forceinline__ ull mul2(ull a, ull b) {
    ull d; asm("mul.rn.f32x2 %0, %1, %2;" : "=l"(d) : "l"(a), "l"(b)); return d;
}

// ---------------- conversion kernels ----------------
__global__ void rowconv_kernel(const float* __restrict__ src,
                               __nv_bfloat16* __restrict__ hi,
                               __nv_bfloat16* __restrict__ lo, int n)
{
    int i = blockIdx.x * blockDim.x + threadIdx.x;
    if (i * 4 >= n) return;
    float4 v = *(const float4*)(src + i * 4);
    float vv[4] = {v.x, v.y, v.z, v.w};
#pragma unroll
    for (int j = 0; j < 4; j++) {
        __nv_bfloat16 h = __float2bfloat16(vv[j]);
        hi[i * 4 + j] = h;
        lo[i * 4 + j] = __float2bfloat16(vv[j] - __bfloat162float(h));
    }
}

// W [K,N] fp32 -> T [N,K] bf16 hi/lo (transpose + split)
__global__ void transconv_kernel(const float* __restrict__ W,
                                 __nv_bfloat16* __restrict__ Thi,
                                 __nv_bfloat16* __restrict__ Tlo, int K, int N)
{
    __shared__ float s[32][33];
    int tx = threadIdx.x, ty = threadIdx.y;
    int n0 = blockIdx.x * 32, k0 = blockIdx.y * 32;
#pragma unroll
    for (int i = 0; i < 4; i++)
        s[ty + i * 8][tx] = W[(size_t)(k0 + ty + i * 8) * N + n0 + tx];
    __syncthreads();
#pragma unroll
    for (int i = 0; i < 4; i++) {
        int n = n0 + ty + i * 8, k = k0 + tx;
        float v = s[tx][ty + i * 8];
        __nv_bfloat16 h = __float2bfloat16(v);
        Thi[(size_t)n * K + k] = h;
        Tlo[(size_t)n * K + k] = __float2bfloat16(v - __bfloat162float(h));
    }
}

// ---------------- mma.sync split-bf16 GEMM ----------------
// C[M,N] = (Ahi+Alo)[M,K] @ (Bhi+Blo)[N,K]^T, dropping lo*lo.
// 128x128 block tile, BK=32, 8 warps (2x4), warp tile 64x32, 2 CTAs/SM.
#define ROWB      80
#define TILE_B    (128 * ROWB)
#define BUF_B     (4 * TILE_B)
#define GEMM_SMEM (2 * BUF_B)              // 81920

template<int KCHUNKS, bool RELU, bool BIAS, bool HILO>
__global__ __launch_bounds__(256, 2)
void mma_gemm(const __nv_bfloat16* __restrict__ Ahi, const __nv_bfloat16* __restrict__ Alo,
              const __nv_bfloat16* __restrict__ Bhi, const __nv_bfloat16* __restrict__ Blo,
              const float* __restrict__ bias,
              float* __restrict__ Cout,
              __nv_bfloat16* __restrict__ Chi, __nv_bfloat16* __restrict__ Clo,
              int M, int N, int K)
{
    extern __shared__ char smem[];
    const uint32_t sbase = smem_u32(smem);
    const int tid  = threadIdx.x;
    const int lane = tid & 31, wid = tid >> 5;
    const int warp_m = wid >> 2;          // 0..1
    const int warp_n = wid & 3;           // 0..3
    const int bn = blockIdx.x * 128;
    const int bm = blockIdx.y * 128;

    const __nv_bfloat16* srcs[4] = {Ahi, Alo, Bhi, Blo};

    auto load_chunk = [&](int c, int buf) {
#pragma unroll
        for (int w = 0; w < 4; w++) {
            const int rowbase = (w < 2) ? bm : bn;
            const __nv_bfloat16* src = srcs[w];
#pragma unroll
            for (int t = 0; t < 2; t++) {
                int idx = tid + t * 256;
                int row = idx >> 2, seg = idx & 3;
                char* dst = smem + buf * BUF_B + w * TILE_B + row * ROWB + seg * 16;
                const char* s = (const char*)src +
                    ((size_t)(rowbase + row) * K + (size_t)c * 32) * 2 + seg * 16;
                __pipeline_memcpy_async(dst, s, 16);
            }
        }
    };

    float acc[4][4][4];
#pragma unroll
    for (int i = 0; i < 4; i++)
#pragma unroll
        for (int j = 0; j < 4; j++)
#pragma unroll
            for (int q = 0; q < 4; q++) acc[i][j][q] = 0.f;

    load_chunk(0, 0);
    __pipeline_commit();
    __pipeline_wait_prior(0);
    __syncthreads();

    const uint32_t a_lane_off = (uint32_t)((lane & 15) * ROWB + (lane >> 4) * 16);
    const uint32_t b_lane_off = (uint32_t)((lane & 7) * ROWB + ((lane >> 3) & 1) * 16);

    for (int c = 0; c < KCHUNKS; c++) {
        if (c + 1 < KCHUNKS) { load_chunk(c + 1, (c + 1) & 1); __pipeline_commit(); }

        const uint32_t bufb = sbase + (c & 1) * BUF_B;
#pragma unroll
        for (int s = 0; s < 2; s++) {
            uint32_t ah[4][4], al[4][4];
            const uint32_t ks = s * 32;
#pragma unroll
            for (int i = 0; i < 4; i++) {
                uint32_t ro = (uint32_t)((warp_m * 64 + i * 16) * ROWB) + ks + a_lane_off;
                ldsm_x4(ah[i], bufb + 0 * TILE_B + ro);
                ldsm_x4(al[i], bufb + 1 * TILE_B + ro);
            }
#pragma unroll
            for (int j = 0; j < 4; j++) {
                uint32_t bh[2], bl[2];
                uint32_t ro = (uint32_t)((warp_n * 32 + j * 8) * ROWB) + ks + b_lane_off;
                ldsm_x2(bh, bufb + 2 * TILE_B + ro);
                ldsm_x2(bl, bufb + 3 * TILE_B + ro);
#pragma unroll
                for (int i = 0; i < 4; i++) {
                    mma_bf16(acc[i][j], ah[i], bh);
                    mma_bf16(acc[i][j], ah[i], bl);
                    mma_bf16(acc[i][j], al[i], bh);
                }
            }
        }
        if (c + 1 < KCHUNKS) __pipeline_wait_prior(0);
        __syncthreads();
    }

    const int r0 = lane >> 2;
    const int q0 = (lane & 3) * 2;
#pragma unroll
    for (int j = 0; j < 4; j++) {
        const int n0 = bn + warp_n * 32 + j * 8 + q0;
        float b0 = BIAS ? bias[n0] : 0.f;
        float b1 = BIAS ? bias[n0 + 1] : 0.f;
#pragma unroll
        for (int i = 0; i < 4; i++) {
            const int m0 = bm + warp_m * 64 + i * 16 + r0;
            float v0 = acc[i][j][0] + b0, v1 = acc[i][j][1] + b1;
            float v2 = acc[i][j][2] + b0, v3 = acc[i][j][3] + b1;
            if (RELU) { v0 = fmaxf(v0, 0.f); v1 = fmaxf(v1, 0.f);
                        v2 = fmaxf(v2, 0.f); v3 = fmaxf(v3, 0.f); }
            *(float2*)&Cout[(size_t)m0 * N + n0]       = make_float2(v0, v1);
            *(float2*)&Cout[(size_t)(m0 + 8) * N + n0] = make_float2(v2, v3);
            if (HILO) {
                __nv_bfloat16 h0 = __float2bfloat16(v0), h1 = __float2bfloat16(v1);
                __nv_bfloat16 h2 = __float2bfloat16(v2), h3 = __float2bfloat16(v3);
                __nv_bfloat162 hp0 = {h0, h1}, hp1 = {h2, h3};
                __nv_bfloat162 lp0 = {__float2bfloat16(v0 - __bfloat162float(h0)),
                                      __float2bfloat16(v1 - __bfloat162float(h1))};
                __nv_bfloat162 lp1 = {__float2bfloat16(v2 - __bfloat162float(h2)),
                                      __float2bfloat16(v3 - __bfloat162float(h3))};
                *(__nv_bfloat162*)&Chi[(size_t)m0 * N + n0]       = hp0;
                *(__nv_bfloat162*)&Chi[(size_t)(m0 + 8) * N + n0] = hp1;
                *(__nv_bfloat162*)&Clo[(size_t)m0 * N + n0]       = lp0;
                *(__nv_bfloat162*)&Clo[(size_t)(m0 + 8) * N + n0] = lp1;
            }
        }
    }
}

// ---------------- dt projection + softplus + decay ----------------
__global__ __launch_bounds__(256)
void dtdecay_kernel(const float* __restrict__ X, const float* __restrict__ W_dt,
                    const float* __restrict__ dt_bias, const float* __restrict__ A_log,
                    float* __restrict__ dts, float* __restrict__ decs)
{
    __shared__ float Xs[16][64];
    __shared__ float Ws[64][16];
    const int tid = threadIdx.x;
    const int m0  = blockIdx.x * 16;
    const int h   = tid & 15;
    const int mi  = tid >> 4;

    float acc = 0.f;
    for (int k0 = 0; k0 < D_IN; k0 += 64) {
        __syncthreads();
        *(float4*)&Xs[tid >> 4][(tid & 15) * 4] =
            *(const float4*)&X[(size_t)(m0 + (tid >> 4)) * D_IN + k0 + (tid & 15) * 4];
        *(float4*)&Ws[tid >> 2][(tid & 3) * 4] =
            *(const float4*)&W_dt[(size_t)(k0 + (tid >> 2)) * NHEAD + (tid & 3) * 4];
        __syncthreads();
#pragma unroll
        for (int k = 0; k < 64; k++)
            acc = fmaf(Xs[mi][k], Ws[k][h], acc);
    }
    const int m = m0 + mi;
    float v  = acc + dt_bias[h];
    float dt = (v > 20.f) ? v : log1pf(expf(v));
    float A  = expf(A_log[h]);
    dts[m * NHEAD + h]  = dt;
    decs[m * NHEAD + h] = expf(-A * dt);
}

// ---------------- selective scan (packed f32x2 state) ----------------
__global__ __launch_bounds__(128, 1)
void scan_kernel(const float* __restrict__ X, const float* __restrict__ Bm,
                 const float* __restrict__ Cm, const float* __restrict__ dts,
                 const float* __restrict__ decs,
                 __nv_bfloat16* __restrict__ Yhi, __nv_bfloat16* __restrict__ Ylo)
{
    const int bh = blockIdx.x;
    const int b  = bh >> 4;
    const int h  = bh & 15;
    const int tid = threadIdx.x;

    __shared__ __align__(16) float xb[4][PHEAD];
    __shared__ __align__(16) float Bb[4][NSTATE];
    __shared__ __align__(16) float Cb[4][NSTATE];
    __shared__ float sc[4][2];

    ull hs2[32];
#pragma unroll
    for (int i = 0; i < 32; i++) hs2[i] = 0ull;

    auto issue = [&](int t) {
        const int st = t & 3;
        const size_t m = (size_t)t * BSZ + b;
        __pipeline_memcpy_async(&xb[st][tid], X + m * D_IN + h * PHEAD + tid, 4);
        if (tid < 64)
            __pipeline_memcpy_async(&Bb[st][tid], Bm + m * HN + h * NSTATE + tid, 4);
        else
            __pipeline_memcpy_async(&Cb[st][tid - 64], Cm + m * HN + h * NSTATE + (tid - 64), 4);
        if (tid == 0) __pipeline_memcpy_async(&sc[st][0], dts  + m * NHEAD + h, 4);
        if (tid == 1) __pipeline_memcpy_async(&sc[st][1], decs + m * NHEAD + h, 4);
    };

    issue(0); __pipeline_commit();
    issue(1); __pipeline_commit();
    issue(2); __pipeline_commit();

    for (int t = 0; t < T_LEN; t++) {
        const int st = t & 3;
        __pipeline_wait_prior(2);
        __syncthreads();
        if (t + 3 < T_LEN) issue(t + 3);
        __pipeline_commit();

        const float dtv = sc[st][0];
        const float dec = sc[st][1];
        const float cc  = dtv * xb[st][tid];
        const ull dec2 = pk2(dec, dec);
        const ull cc2  = pk2(cc, cc);

        const longlong2* B2 = (const longlong2*)Bb[st];
        const longlong2* C2 = (const longlong2*)Cb[st];
        ull ya = 0ull, yb = 0ull;
#pragma unroll
        for (int j = 0; j < 16; j++) {
            longlong2 bv = B2[j];
            longlong2 cv = C2[j];
            hs2[2*j]   = fma2(dec2, hs2[2*j],   mul2(cc2, (ull)bv.x));
            ya         = fma2(hs2[2*j],   (ull)cv.x, ya);
            hs2[2*j+1] = fma2(dec2, hs2[2*j+1], mul2(cc2, (ull)bv.y));
            yb         = fma2(hs2[2*j+1], (ull)cv.y, yb);
        }
        float a0, a1, c0, c1;
        upk2(a0, a1, ya);
        upk2(c0, c1, yb);
        const float y = (a0 + a1) + (c0 + c1);

        const size_t m = (size_t)t * BSZ + b;
        __nv_bfloat16 hy = __float2bfloat16(y);
        Yhi[m * D_IN + h * PHEAD + tid] = hy;
        Ylo[m * D_IN + h * PHEAD + tid] = __float2bfloat16(y - __bfloat162float(hy));
    }
}

// ---------------- policy head ----------------
__global__ __launch_bounds__(256)
void head_kernel(const float* __restrict__ Z, const float* __restrict__ Wh,
                 const float* __restrict__ bh, float* __restrict__ out)
{
    __shared__ float Zs[4][NUNITS];
    __shared__ float Ws[64][NACT];
    const int tid = threadIdx.x;
    const int m0  = blockIdx.x * 4;
    const int n   = tid & 63;
    const int mi  = tid >> 6;

    *(float4*)&Zs[tid >> 6][(tid & 63) * 4] =
        *(const float4*)&Z[(size_t)(m0 + (tid >> 6)) * NUNITS + (tid & 63) * 4];

    float acc = bh[n];
    for (int k0 = 0; k0 < NUNITS; k0 += 64) {
        __syncthreads();
#pragma unroll
        for (int j = 0; j < 4; j++) {
            int idx = tid + j * 256;
            int r = idx >> 4, c4 = (idx & 15) * 4;
            *(float4*)&Ws[r][c4] = *(const float4*)&Wh[(size_t)(k0 + r) * NACT + c4];
        }
        __syncthreads();
#pragma unroll
        for (int k = 0; k < 64; k++)
            acc = fmaf(Zs[mi][k0 + k], Ws[k][n], acc);
    }
    out[(size_t)(m0 + mi) * NACT + n] = acc;
}

// ---------------- launch ----------------
extern "C" void kernel_launch(void* const* d_in, const int* in_sizes, int n_in,
                              void* d_out, int out_size)
{
    const float* obs     = (const float*)d_in[0];
    const float* W_in    = (const float*)d_in[1];
    const float* b_in    = (const float*)d_in[2];
    const float* A_log   = (const float*)d_in[3];
    const float* dt_bias = (const float*)d_in[4];
    const float* W_dt    = (const float*)d_in[5];
    const float* W_B     = (const float*)d_in[6];
    const float* W_C     = (const float*)d_in[7];
    const float* W_yo    = (const float*)d_in[8];
    const float* b_yo    = (const float*)d_in[9];
    const float* W_head  = (const float*)d_in[10];
    const float* b_head  = (const float*)d_in[11];
    float* out = (float*)d_out;

    float *X, *Bmp, *Cmp, *dts, *dec, *Z;
    __nv_bfloat16 *Xhi, *Xlo, *Yhi, *Ylo, *obsh, *obsl;
    __nv_bfloat16 *Winh, *Winl, *WBh, *WBl, *WCh, *WCl, *Wyoh, *Wyol;
    cudaGetSymbolAddress((void**)&X,    g_X);
    cudaGetSymbolAddress((void**)&Xhi,  g_Xhi);
    cudaGetSymbolAddress((void**)&Xlo,  g_Xlo);
    cudaGetSymbolAddress((void**)&Bmp,  g_Bm);
    cudaGetSymbolAddress((void**)&Cmp,  g_Cm);
    cudaGetSymbolAddress((void**)&dts,  g_dt);
    cudaGetSymbolAddress((void**)&dec,  g_dec);
    cudaGetSymbolAddress((void**)&Yhi,  g_Yhi);
    cudaGetSymbolAddress((void**)&Ylo,  g_Ylo);
    cudaGetSymbolAddress((void**)&Z,    g_Z);
    cudaGetSymbolAddress((void**)&obsh, g_obs_hi);
    cudaGetSymbolAddress((void**)&obsl, g_obs_lo);
    cudaGetSymbolAddress((void**)&Winh, g_Win_hi);
    cudaGetSymbolAddress((void**)&Winl, g_Win_lo);
    cudaGetSymbolAddress((void**)&WBh,  g_WB_hi);
    cudaGetSymbolAddress((void**)&WBl,  g_WB_lo);
    cudaGetSymbolAddress((void**)&WCh,  g_WC_hi);
    cudaGetSymbolAddress((void**)&WCl,  g_WC_lo);
    cudaGetSymbolAddress((void**)&Wyoh, g_Wyo_hi);
    cudaGetSymbolAddress((void**)&Wyol, g_Wyo_lo);

    cudaFuncSetAttribute(mma_gemm<8,  true,  true,  true >, cudaFuncAttributeMaxDynamicSharedMemorySize, GEMM_SMEM);
    cudaFuncSetAttribute(mma_gemm<64, false, false, false>, cudaFuncAttributeMaxDynamicSharedMemorySize, GEMM_SMEM);
    cudaFuncSetAttribute(mma_gemm<64, true,  true,  false>, cudaFuncAttributeMaxDynamicSharedMemorySize, GEMM_SMEM);

    // 0) operand conversions
    rowconv_kernel<<<(M_TOT * OBS_DIM / 4 + 255) / 256, 256>>>(obs, obsh, obsl, M_TOT * OBS_DIM);
    transconv_kernel<<<dim3(D_IN / 32, OBS_DIM / 32), dim3(32, 8)>>>(W_in, Winh, Winl, OBS_DIM, D_IN);
    transconv_kernel<<<dim3(HN / 32,  D_IN / 32),   dim3(32, 8)>>>(W_B,  WBh,  WBl,  D_IN, HN);
    transconv_kernel<<<dim3(HN / 32,  D_IN / 32),   dim3(32, 8)>>>(W_C,  WCh,  WCl,  D_IN, HN);
    transconv_kernel<<<dim3(NUNITS / 32, D_IN / 32), dim3(32, 8)>>>(W_yo, Wyoh, Wyol, D_IN, NUNITS);

    // 1) X = relu(obs @ W_in + b_in)  [4096 x 2048, K=256]  (+ hi/lo split)
    mma_gemm<8, true, true, true><<<dim3(D_IN / 128, M_TOT / 128), 256, GEMM_SMEM>>>(
        obsh, obsl, Winh, Winl, b_in, X, Xhi, Xlo, M_TOT, D_IN, OBS_DIM);

    // 2) dt / decay
    dtdecay_kernel<<<M_TOT / 16, 256>>>(X, W_dt, dt_bias, A_log, dts, dec);

    // 3) B = X @ W_B, C = X @ W_C  [4096 x 1024, K=2048]
    mma_gemm<64, false, false, false><<<dim3(HN / 128, M_TOT / 128), 256, GEMM_SMEM>>>(
        Xhi, Xlo, WBh, WBl, nullptr, Bmp, nullptr, nullptr, M_TOT, HN, D_IN);
    mma_gemm<64, false, false, false><<<dim3(HN / 128, M_TOT / 128), 256, GEMM_SMEM>>>(
        Xhi, Xlo, WCh, WCl, nullptr, Cmp, nullptr, nullptr, M_TOT, HN, D_IN);

    // 4) selective scan -> Y (hi/lo)
    scan_kernel<<<BSZ * NHEAD, 128>>>(X, Bmp, Cmp, dts, dec, Yhi, Ylo);

    // 5) Z = relu(Y @ W_yo + b_yo)  [4096 x 256, K=2048]
    mma_gemm<64, true, true, false><<<dim3(NUNITS / 128, M_TOT / 128), 256, GEMM_SMEM>>>(
        Yhi, Ylo, Wyoh, Wyol, b_yo, Z, nullptr, nullptr, M_TOT, NUNITS, D_IN);

    // 6) logits = Z @ W_head + b_head
    head_kernel<<<M_TOT / 4, 256>>>(Z, W_head, b_head, out);
}

// round 5
// speedup vs baseline: 4.2925x; 1.0181x over previous
#include <cuda_runtime.h>
#include <cuda_pipeline.h>
#include <cuda_bf16.h>
#include <math.h>
#include <stdint.h>

// ---------------- problem dims ----------------
#define T_LEN   512
#define BSZ     8
#define M_TOT   (T_LEN * BSZ)      // 4096
#define OBS_DIM 256
#define D_IN    2048
#define NHEAD   16
#define NSTATE  64
#define PHEAD   128                 // D_IN / NHEAD
#define NUNITS  256
#define NACT    64
#define HN      (NHEAD * NSTATE)    // 1024

// ---------------- scratch (device globals; allocation-free) ----------------
__device__ float          g_X   [M_TOT * D_IN];
__device__ __nv_bfloat16  g_Xhi [M_TOT * D_IN];
__device__ __nv_bfloat16  g_Xlo [M_TOT * D_IN];
__device__ float          g_Bm  [M_TOT * HN];
__device__ float          g_Cm  [M_TOT * HN];
__device__ float          g_dt  [M_TOT * NHEAD];
__device__ float          g_dec [M_TOT * NHEAD];
__device__ __nv_bfloat16  g_Yhi [M_TOT * D_IN];
__device__ __nv_bfloat16  g_Ylo [M_TOT * D_IN];
__device__ float          g_Z   [M_TOT * NUNITS];
__device__ __nv_bfloat16  g_obs_hi[M_TOT * OBS_DIM];
__device__ __nv_bfloat16  g_obs_lo[M_TOT * OBS_DIM];
__device__ __nv_bfloat16  g_Win_hi[D_IN * OBS_DIM];   // [N,K]
__device__ __nv_bfloat16  g_Win_lo[D_IN * OBS_DIM];
__device__ __nv_bfloat16  g_WB_hi [HN * D_IN];
__device__ __nv_bfloat16  g_WB_lo [HN * D_IN];
__device__ __nv_bfloat16  g_WC_hi [HN * D_IN];
__device__ __nv_bfloat16  g_WC_lo [HN * D_IN];
__device__ __nv_bfloat16  g_Wyo_hi[NUNITS * D_IN];
__device__ __nv_bfloat16  g_Wyo_lo[NUNITS * D_IN];

// ---------------- low-level helpers (base sm_103 target legal) -------------
__device__ __forceinline__ uint32_t smem_u32(const void* p) {
    uint32_t a;
    asm("{ .reg .u64 t; cvta.to.shared.u64 t, %1; cvt.u32.u64 %0, t; }" : "=r"(a) : "l"(p));
    return a;
}
__device__ __forceinline__ void ldsm_x4(uint32_t* r, uint32_t addr) {
    asm volatile("ldmatrix.sync.aligned.m8n8.x4.shared.b16 {%0,%1,%2,%3}, [%4];"
                 : "=r"(r[0]), "=r"(r[1]), "=r"(r[2]), "=r"(r[3]) : "r"(addr));
}
__device__ __forceinline__ void ldsm_x2(uint32_t* r, uint32_t addr) {
    asm volatile("ldmatrix.sync.aligned.m8n8.x2.shared.b16 {%0,%1}, [%2];"
                 : "=r"(r[0]), "=r"(r[1]) : "r"(addr));
}
__device__ __forceinline__ void mma_bf16(float* c, const uint32_t* a, const uint32_t* b) {
    asm volatile("mma.sync.aligned.m16n8k16.row.col.f32.bf16.bf16.f32 "
                 "{%0,%1,%2,%3}, {%4,%5,%6,%7}, {%8,%9}, {%0,%1,%2,%3};"
                 : "+f"(c[0]), "+f"(c[1]), "+f"(c[2]), "+f"(c[3])
                 : "r"(a[0]), "r"(a[1]), "r"(a[2]), "r"(a[3]), "r"(b[0]), "r"(b[1]));
}
// packed f32x2 (PTX 8.6, sm_100+ base ISA -> SASS FFMA2)
typedef unsigned long long ull;
__device__ __forceinline__ ull pk2(float lo, float hi) {
    ull r; asm("mov.b64 %0, {%1, %2};" : "=l"(r) : "f"(lo), "f"(hi)); return r;
}
__device__ __forceinline__ void upk2(float& lo, float& hi, ull v) {
    asm("mov.b64 {%0, %1}, %2;" : "=f"(lo), "=f"(hi) : "l"(v));
}
__device__ __forceinline__ ull fma2(ull a, ull b, ull c) {
    ull d; asm("fma.rn.f32x2 %0, %1, %2, %3;" : "=l"(d) : "l"(a), "l"(b), "l"(c)); return d;
}
__device__ __forceinline__ ull mul2(ull a, ull b) {
    ull d; asm("mul.rn.f32x2 %0, %1, %2;" : "=l"(d) : "l"(a), "l"(b)); return d;
}

// ---------------- conversion kernels ----------------
__global__ void rowconv_kernel(const float* __restrict__ src,
                               __nv_bfloat16* __restrict__ hi,
                               __nv_bfloat16* __restrict__ lo, int n)
{
    int i = blockIdx.x * blockDim.x + threadIdx.x;
    if (i * 4 >= n) return;
    float4 v = *(const float4*)(src + i * 4);
    float vv[4] = {v.x, v.y, v.z, v.w};
#pragma unroll
    for (int j = 0; j < 4; j++) {
        __nv_bfloat16 h = __float2bfloat16(vv[j]);
        hi[i * 4 + j] = h;
        lo[i * 4 + j] = __float2bfloat16(vv[j] - __bfloat162float(h));
    }
}

// W [K,N] fp32 -> T [N,K] bf16 hi/lo (transpose + split)
__global__ void transconv_kernel(const float* __restrict__ W,
                                 __nv_bfloat16* __restrict__ Thi,
                                 __nv_bfloat16* __restrict__ Tlo, int K, int N)
{
    __shared__ float s[32][33];
    int tx = threadIdx.x, ty = threadIdx.y;
    int n0 = blockIdx.x * 32, k0 = blockIdx.y * 32;
#pragma unroll
    for (int i = 0; i < 4; i++)
        s[ty + i * 8][tx] = W[(size_t)(k0 + ty + i * 8) * N + n0 + tx];
    __syncthreads();
#pragma unroll
    for (int i = 0; i < 4; i++) {
        int n = n0 + ty + i * 8, k = k0 + tx;
        float v = s[tx][ty + i * 8];
        __nv_bfloat16 h = __float2bfloat16(v);
        Thi[(size_t)n * K + k] = h;
        Tlo[(size_t)n * K + k] = __float2bfloat16(v - __bfloat162float(h));
    }
}

// ---------------- mma.sync split-bf16 GEMM ----------------
#define ROWB      80
#define TILE_B    (128 * ROWB)
#define BUF_B     (4 * TILE_B)
#define GEMM_SMEM (2 * BUF_B)              // 81920

template<int KCHUNKS, bool RELU, bool BIAS, bool HILO>
__global__ __launch_bounds__(256, 2)
void mma_gemm(const __nv_bfloat16* __restrict__ Ahi, const __nv_bfloat16* __restrict__ Alo,
              const __nv_bfloat16* __restrict__ Bhi, const __nv_bfloat16* __restrict__ Blo,
              const float* __restrict__ bias,
              float* __restrict__ Cout,
              __nv_bfloat16* __restrict__ Chi, __nv_bfloat16* __restrict__ Clo,
              int M, int N, int K)
{
    extern __shared__ char smem[];
    const uint32_t sbase = smem_u32(smem);
    const int tid  = threadIdx.x;
    const int lane = tid & 31, wid = tid >> 5;
    const int warp_m = wid >> 2;
    const int warp_n = wid & 3;
    const int bn = blockIdx.x * 128;
    const int bm = blockIdx.y * 128;

    const __nv_bfloat16* srcs[4] = {Ahi, Alo, Bhi, Blo};

    auto load_chunk = [&](int c, int buf) {
#pragma unroll
        for (int w = 0; w < 4; w++) {
            const int rowbase = (w < 2) ? bm : bn;
            const __nv_bfloat16* src = srcs[w];
#pragma unroll
            for (int t = 0; t < 2; t++) {
                int idx = tid + t * 256;
                int row = idx >> 2, seg = idx & 3;
                char* dst = smem + buf * BUF_B + w * TILE_B + row * ROWB + seg * 16;
                const char* s = (const char*)src +
                    ((size_t)(rowbase + row) * K + (size_t)c * 32) * 2 + seg * 16;
                __pipeline_memcpy_async(dst, s, 16);
            }
        }
    };

    float acc[4][4][4];
#pragma unroll
    for (int i = 0; i < 4; i++)
#pragma unroll
        for (int j = 0; j < 4; j++)
#pragma unroll
            for (int q = 0; q < 4; q++) acc[i][j][q] = 0.f;

    load_chunk(0, 0);
    __pipeline_commit();
    __pipeline_wait_prior(0);
    __syncthreads();

    const uint32_t a_lane_off = (uint32_t)((lane & 15) * ROWB + (lane >> 4) * 16);
    const uint32_t b_lane_off = (uint32_t)((lane & 7) * ROWB + ((lane >> 3) & 1) * 16);

    for (int c = 0; c < KCHUNKS; c++) {
        if (c + 1 < KCHUNKS) { load_chunk(c + 1, (c + 1) & 1); __pipeline_commit(); }

        const uint32_t bufb = sbase + (c & 1) * BUF_B;
#pragma unroll
        for (int s = 0; s < 2; s++) {
            uint32_t ah[4][4], al[4][4];
            const uint32_t ks = s * 32;
#pragma unroll
            for (int i = 0; i < 4; i++) {
                uint32_t ro = (uint32_t)((warp_m * 64 + i * 16) * ROWB) + ks + a_lane_off;
                ldsm_x4(ah[i], bufb + 0 * TILE_B + ro);
                ldsm_x4(al[i], bufb + 1 * TILE_B + ro);
            }
#pragma unroll
            for (int j = 0; j < 4; j++) {
                uint32_t bh[2], bl[2];
                uint32_t ro = (uint32_t)((warp_n * 32 + j * 8) * ROWB) + ks + b_lane_off;
                ldsm_x2(bh, bufb + 2 * TILE_B + ro);
                ldsm_x2(bl, bufb + 3 * TILE_B + ro);
#pragma unroll
                for (int i = 0; i < 4; i++) {
                    mma_bf16(acc[i][j], ah[i], bh);
                    mma_bf16(acc[i][j], ah[i], bl);
                    mma_bf16(acc[i][j], al[i], bh);
                }
            }
        }
        if (c + 1 < KCHUNKS) __pipeline_wait_prior(0);
        __syncthreads();
    }

    const int r0 = lane >> 2;
    const int q0 = (lane & 3) * 2;
#pragma unroll
    for (int j = 0; j < 4; j++) {
        const int n0 = bn + warp_n * 32 + j * 8 + q0;
        float b0 = BIAS ? bias[n0] : 0.f;
        float b1 = BIAS ? bias[n0 + 1] : 0.f;
#pragma unroll
        for (int i = 0; i < 4; i++) {
            const int m0 = bm + warp_m * 64 + i * 16 + r0;
            float v0 = acc[i][j][0] + b0, v1 = acc[i][j][1] + b1;
            float v2 = acc[i][j][2] + b0, v3 = acc[i][j][3] + b1;
            if (RELU) { v0 = fmaxf(v0, 0.f); v1 = fmaxf(v1, 0.f);
                        v2 = fmaxf(v2, 0.f); v3 = fmaxf(v3, 0.f); }
            *(float2*)&Cout[(size_t)m0 * N + n0]       = make_float2(v0, v1);
            *(float2*)&Cout[(size_t)(m0 + 8) * N + n0] = make_float2(v2, v3);
            if (HILO) {
                __nv_bfloat16 h0 = __float2bfloat16(v0), h1 = __float2bfloat16(v1);
                __nv_bfloat16 h2 = __float2bfloat16(v2), h3 = __float2bfloat16(v3);
                __nv_bfloat162 hp0 = {h0, h1}, hp1 = {h2, h3};
                __nv_bfloat162 lp0 = {__float2bfloat16(v0 - __bfloat162float(h0)),
                                      __float2bfloat16(v1 - __bfloat162float(h1))};
                __nv_bfloat162 lp1 = {__float2bfloat16(v2 - __bfloat162float(h2)),
                                      __float2bfloat16(v3 - __bfloat162float(h3))};
                *(__nv_bfloat162*)&Chi[(size_t)m0 * N + n0]       = hp0;
                *(__nv_bfloat162*)&Chi[(size_t)(m0 + 8) * N + n0] = hp1;
                *(__nv_bfloat162*)&Clo[(size_t)m0 * N + n0]       = lp0;
                *(__nv_bfloat162*)&Clo[(size_t)(m0 + 8) * N + n0] = lp1;
            }
        }
    }
}

// ---------------- dt projection + softplus + decay ----------------
__global__ __launch_bounds__(256)
void dtdecay_kernel(const float* __restrict__ X, const float* __restrict__ W_dt,
                    const float* __restrict__ dt_bias, const float* __restrict__ A_log,
                    float* __restrict__ dts, float* __restrict__ decs)
{
    __shared__ float Xs[16][64];
    __shared__ float Ws[64][16];
    const int tid = threadIdx.x;
    const int m0  = blockIdx.x * 16;
    const int h   = tid & 15;
    const int mi  = tid >> 4;

    float acc = 0.f;
    for (int k0 = 0; k0 < D_IN; k0 += 64) {
        __syncthreads();
        *(float4*)&Xs[tid >> 4][(tid & 15) * 4] =
            *(const float4*)&X[(size_t)(m0 + (tid >> 4)) * D_IN + k0 + (tid & 15) * 4];
        *(float4*)&Ws[tid >> 2][(tid & 3) * 4] =
            *(const float4*)&W_dt[(size_t)(k0 + (tid >> 2)) * NHEAD + (tid & 3) * 4];
        __syncthreads();
#pragma unroll
        for (int k = 0; k < 64; k++)
            acc = fmaf(Xs[mi][k], Ws[k][h], acc);
    }
    const int m = m0 + mi;
    float v  = acc + dt_bias[h];
    float dt = (v > 20.f) ? v : log1pf(expf(v));
    float A  = expf(A_log[h]);
    dts[m * NHEAD + h]  = dt;
    decs[m * NHEAD + h] = expf(-A * dt);
}

// ---------------- selective scan (packed f32x2 state) ----------------
__global__ __launch_bounds__(128, 1)
void scan_kernel(const float* __restrict__ X, const float* __restrict__ Bm,
                 const float* __restrict__ Cm, const float* __restrict__ dts,
                 const float* __restrict__ decs,
                 __nv_bfloat16* __restrict__ Yhi, __nv_bfloat16* __restrict__ Ylo)
{
    const int bh = blockIdx.x;
    const int b  = bh >> 4;
    const int h  = bh & 15;
    const int tid = threadIdx.x;

    __shared__ __align__(16) float xb[4][PHEAD];
    __shared__ __align__(16) float Bb[4][NSTATE];
    __shared__ __align__(16) float Cb[4][NSTATE];
    __shared__ float sc[4][2];

    ull hs2[32];
#pragma unroll
    for (int i = 0; i < 32; i++) hs2[i] = 0ull;

    auto issue = [&](int t) {
        const int st = t & 3;
        const size_t m = (size_t)t * BSZ + b;
        __pipeline_memcpy_async(&xb[st][tid], X + m * D_IN + h * PHEAD + tid, 4);
        if (tid < 64)
            __pipeline_memcpy_async(&Bb[st][tid], Bm + m * HN + h * NSTATE + tid, 4);
        else
            __pipeline_memcpy_async(&Cb[st][tid - 64], Cm + m * HN + h * NSTATE + (tid - 64), 4);
        if (tid == 0) __pipeline_memcpy_async(&sc[st][0], dts  + m * NHEAD + h, 4);
        if (tid == 1) __pipeline_memcpy_async(&sc[st][1], decs + m * NHEAD + h, 4);
    };

    issue(0); __pipeline_commit();
    issue(1); __pipeline_commit();
    issue(2); __pipeline_commit();

    for (int t = 0; t < T_LEN; t++) {
        const int st = t & 3;
        __pipeline_wait_prior(2);
        __syncthreads();
        if (t + 3 < T_LEN) issue(t + 3);
        __pipeline_commit();

        const float dtv = sc[st][0];
        const float dec = sc[st][1];
        const float cc  = dtv * xb[st][tid];
        const ull dec2 = pk2(dec, dec);
        const ull cc2  = pk2(cc, cc);

        const longlong2* B2 = (const longlong2*)Bb[st];
        const longlong2* C2 = (const longlong2*)Cb[st];
        ull ya = 0ull, yb = 0ull;
#pragma unroll
        for (int j = 0; j < 16; j++) {
            longlong2 bv = B2[j];
            longlong2 cv = C2[j];
            hs2[2*j]   = fma2(dec2, hs2[2*j],   mul2(cc2, (ull)bv.x));
            ya         = fma2(hs2[2*j],   (ull)cv.x, ya);
            hs2[2*j+1] = fma2(dec2, hs2[2*j+1], mul2(cc2, (ull)bv.y));
            yb         = fma2(hs2[2*j+1], (ull)cv.y, yb);
        }
        float a0, a1, c0, c1;
        upk2(a0, a1, ya);
        upk2(c0, c1, yb);
        const float y = (a0 + a1) + (c0 + c1);

        const size_t m = (size_t)t * BSZ + b;
        __nv_bfloat16 hy = __float2bfloat16(y);
        Yhi[m * D_IN + h * PHEAD + tid] = hy;
        Ylo[m * D_IN + h * PHEAD + tid] = __float2bfloat16(y - __bfloat162float(hy));
    }
}

// ---------------- policy head ----------------
__global__ __launch_bounds__(256)
void head_kernel(const float* __restrict__ Z, const float* __restrict__ Wh,
                 const float* __restrict__ bh, float* __restrict__ out)
{
    __shared__ float Zs[4][NUNITS];
    __shared__ float Ws[64][NACT];
    const int tid = threadIdx.x;
    const int m0  = blockIdx.x * 4;
    const int n   = tid & 63;
    const int mi  = tid >> 6;

    *(float4*)&Zs[tid >> 6][(tid & 63) * 4] =
        *(const float4*)&Z[(size_t)(m0 + (tid >> 6)) * NUNITS + (tid & 63) * 4];

    float acc = bh[n];
    for (int k0 = 0; k0 < NUNITS; k0 += 64) {
        __syncthreads();
#pragma unroll
        for (int j = 0; j < 4; j++) {
            int idx = tid + j * 256;
            int r = idx >> 4, c4 = (idx & 15) * 4;
            *(float4*)&Ws[r][c4] = *(const float4*)&Wh[(size_t)(k0 + r) * NACT + c4];
        }
        __syncthreads();
#pragma unroll
        for (int k = 0; k < 64; k++)
            acc = fmaf(Zs[mi][k0 + k], Ws[k][n], acc);
    }
    out[(size_t)(m0 + mi) * NACT + n] = acc;
}

// ---------------- launch (multi-stream fork/join, graph-capturable) --------
extern "C" void kernel_launch(void* const* d_in, const int* in_sizes, int n_in,
                              void* d_out, int out_size)
{
    const float* obs     = (const float*)d_in[0];
    const float* W_in    = (const float*)d_in[1];
    const float* b_in    = (const float*)d_in[2];
    const float* A_log   = (const float*)d_in[3];
    const float* dt_bias = (const float*)d_in[4];
    const float* W_dt    = (const float*)d_in[5];
    const float* W_B     = (const float*)d_in[6];
    const float* W_C     = (const float*)d_in[7];
    const float* W_yo    = (const float*)d_in[8];
    const float* b_yo    = (const float*)d_in[9];
    const float* W_head  = (const float*)d_in[10];
    const float* b_head  = (const float*)d_in[11];
    float* out = (float*)d_out;

    float *X, *Bmp, *Cmp, *dts, *dec, *Z;
    __nv_bfloat16 *Xhi, *Xlo, *Yhi, *Ylo, *obsh, *obsl;
    __nv_bfloat16 *Winh, *Winl, *WBh, *WBl, *WCh, *WCl, *Wyoh, *Wyol;
    cudaGetSymbolAddress((void**)&X,    g_X);
    cudaGetSymbolAddress((void**)&Xhi,  g_Xhi);
    cudaGetSymbolAddress((void**)&Xlo,  g_Xlo);
    cudaGetSymbolAddress((void**)&Bmp,  g_Bm);
    cudaGetSymbolAddress((void**)&Cmp,  g_Cm);
    cudaGetSymbolAddress((void**)&dts,  g_dt);
    cudaGetSymbolAddress((void**)&dec,  g_dec);
    cudaGetSymbolAddress((void**)&Yhi,  g_Yhi);
    cudaGetSymbolAddress((void**)&Ylo,  g_Ylo);
    cudaGetSymbolAddress((void**)&Z,    g_Z);
    cudaGetSymbolAddress((void**)&obsh, g_obs_hi);
    cudaGetSymbolAddress((void**)&obsl, g_obs_lo);
    cudaGetSymbolAddress((void**)&Winh, g_Win_hi);
    cudaGetSymbolAddress((void**)&Winl, g_Win_lo);
    cudaGetSymbolAddress((void**)&WBh,  g_WB_hi);
    cudaGetSymbolAddress((void**)&WBl,  g_WB_lo);
    cudaGetSymbolAddress((void**)&WCh,  g_WC_hi);
    cudaGetSymbolAddress((void**)&WCl,  g_WC_lo);
    cudaGetSymbolAddress((void**)&Wyoh, g_Wyo_hi);
    cudaGetSymbolAddress((void**)&Wyol, g_Wyo_lo);

    // one-time stream/event creation (first call is the non-captured
    // correctness run, so nothing is created during graph capture)
    static cudaStream_t sB = nullptr, sC = nullptr;
    static cudaEvent_t eFork, eWB, eWC, eWyo, eX, eC, eD;
    if (!sB) {
        cudaStreamCreateWithFlags(&sB, cudaStreamNonBlocking);
        cudaStreamCreateWithFlags(&sC, cudaStreamNonBlocking);
        cudaEventCreateWithFlags(&eFork, cudaEventDisableTiming);
        cudaEventCreateWithFlags(&eWB,  cudaEventDisableTiming);
        cudaEventCreateWithFlags(&eWC,  cudaEventDisableTiming);
        cudaEventCreateWithFlags(&eWyo, cudaEventDisableTiming);
        cudaEventCreateWithFlags(&eX,   cudaEventDisableTiming);
        cudaEventCreateWithFlags(&eC,   cudaEventDisableTiming);
        cudaEventCreateWithFlags(&eD,   cudaEventDisableTiming);

        cudaFuncSetAttribute(mma_gemm<8,  true,  true,  true >, cudaFuncAttributeMaxDynamicSharedMemorySize, GEMM_SMEM);
        cudaFuncSetAttribute(mma_gemm<64, false, false, false>, cudaFuncAttributeMaxDynamicSharedMemorySize, GEMM_SMEM);
        cudaFuncSetAttribute(mma_gemm<64, true,  true,  false>, cudaFuncAttributeMaxDynamicSharedMemorySize, GEMM_SMEM);
    }

    // fork side streams off the main stream
    cudaEventRecord(eFork, 0);
    cudaStreamWaitEvent(sB, eFork, 0);
    cudaStreamWaitEvent(sC, eFork, 0);

    // side stream B: W_B conversion (needed by gemmB on main stream)
    transconv_kernel<<<dim3(HN / 32, D_IN / 32), dim3(32, 8), 0, sB>>>(W_B, WBh, WBl, D_IN, HN);
    cudaEventRecord(eWB, sB);
    // side stream C: W_C then W_yo conversions
    transconv_kernel<<<dim3(HN / 32, D_IN / 32), dim3(32, 8), 0, sC>>>(W_C, WCh, WCl, D_IN, HN);
    cudaEventRecord(eWC, sC);
    transconv_kernel<<<dim3(NUNITS / 32, D_IN / 32), dim3(32, 8), 0, sC>>>(W_yo, Wyoh, Wyol, D_IN, NUNITS);
    cudaEventRecord(eWyo, sC);

    // main stream: obs conversion, W_in conversion, GEMM1
    rowconv_kernel<<<(M_TOT * OBS_DIM / 4 + 255) / 256, 256>>>(obs, obsh, obsl, M_TOT * OBS_DIM);
    transconv_kernel<<<dim3(D_IN / 32, OBS_DIM / 32), dim3(32, 8)>>>(W_in, Winh, Winl, OBS_DIM, D_IN);
    mma_gemm<8, true, true, true><<<dim3(D_IN / 128, M_TOT / 128), 256, GEMM_SMEM>>>(
        obsh, obsl, Winh, Winl, b_in, X, Xhi, Xlo, M_TOT, D_IN, OBS_DIM);
    cudaEventRecord(eX, 0);

    // gemmB on main stream (wait for WB conv)
    cudaStreamWaitEvent(0, eWB, 0);
    mma_gemm<64, false, false, false><<<dim3(HN / 128, M_TOT / 128), 256, GEMM_SMEM>>>(
        Xhi, Xlo, WBh, WBl, nullptr, Bmp, nullptr, nullptr, M_TOT, HN, D_IN);

    // gemmC on stream B (wait for X and WC conv), concurrent with gemmB
    cudaStreamWaitEvent(sB, eX, 0);
    cudaStreamWaitEvent(sB, eWC, 0);
    mma_gemm<64, false, false, false><<<dim3(HN / 128, M_TOT / 128), 256, GEMM_SMEM, sB>>>(
        Xhi, Xlo, WCh, WCl, nullptr, Cmp, nullptr, nullptr, M_TOT, HN, D_IN);
    cudaEventRecord(eC, sB);

    // dtdecay on stream C (needs X), concurrent with gemmB/gemmC
    cudaStreamWaitEvent(sC, eX, 0);
    dtdecay_kernel<<<M_TOT / 16, 256, 0, sC>>>(X, W_dt, dt_bias, A_log, dts, dec);
    cudaEventRecord(eD, sC);

    // join: scan needs Bm (main), Cm (sB), dt/dec (sC)
    cudaStreamWaitEvent(0, eC, 0);
    cudaStreamWaitEvent(0, eD, 0);
    scan_kernel<<<BSZ * NHEAD, 128>>>(X, Bmp, Cmp, dts, dec, Yhi, Ylo);

    // output projection + head on main stream (needs Wyo conv)
    cudaStreamWaitEvent(0, eWyo, 0);
    mma_gemm<64, true, true, false><<<dim3(NUNITS / 128, M_TOT / 128), 256, GEMM_SMEM>>>(
        Yhi, Ylo, Wyoh, Wyol, b_yo, Z, nullptr, nullptr, M_TOT, NUNITS, D_IN);
    head_kernel<<<M_TOT / 4, 256>>>(Z, W_head, b_head, out);
}

// round 6
// speedup vs baseline: 5.3967x; 1.2573x over previous
#include <cuda_runtime.h>
#include <cuda_pipeline.h>
#include <cuda_bf16.h>
#include <cuda_fp16.h>
#include <math.h>
#include <stdint.h>

// ---------------- problem dims ----------------
#define T_LEN   512
#define BSZ     8
#define M_TOT   (T_LEN * BSZ)      // 4096
#define OBS_DIM 256
#define D_IN    2048
#define NHEAD   16
#define NSTATE  64
#define PHEAD   128
#define NUNITS  256
#define NACT    64
#define HN      (NHEAD * NSTATE)    // 1024
#define WSCALE  32.0f
#define WISCALE (1.0f / 32.0f)

// ---------------- scratch ----------------
__device__ float          g_X   [M_TOT * D_IN];
__device__ __half         g_Xhi [M_TOT * D_IN];      // fp16 hi of X
__device__ __half         g_Xlo [M_TOT * D_IN];      // fp16 lo of X
__device__ float          g_Bm  [M_TOT * HN];
__device__ float          g_Cm  [M_TOT * HN];
__device__ float          g_dt  [M_TOT * NHEAD];
__device__ float          g_dec [M_TOT * NHEAD];
__device__ __nv_bfloat16  g_Yhi [M_TOT * D_IN];
__device__ __nv_bfloat16  g_Ylo [M_TOT * D_IN];
__device__ float          g_Zp  [2 * M_TOT * NUNITS];   // split-K partials
__device__ __nv_bfloat16  g_obs_hi[M_TOT * OBS_DIM];
__device__ __nv_bfloat16  g_obs_lo[M_TOT * OBS_DIM];
__device__ __nv_bfloat16  g_Win_hi[D_IN * OBS_DIM];
__device__ __nv_bfloat16  g_Win_lo[D_IN * OBS_DIM];
__device__ __half         g_WB_h [HN * D_IN];           // single fp16, x32
__device__ __half         g_WC_h [HN * D_IN];
__device__ __nv_bfloat16  g_Wyo_hi[NUNITS * D_IN];
__device__ __nv_bfloat16  g_Wyo_lo[NUNITS * D_IN];

// ---------------- helpers ----------------
__device__ __forceinline__ uint32_t smem_u32(const void* p) {
    uint32_t a;
    asm("{ .reg .u64 t; cvta.to.shared.u64 t, %1; cvt.u32.u64 %0, t; }" : "=r"(a) : "l"(p));
    return a;
}
__device__ __forceinline__ void ldsm_x4(uint32_t* r, uint32_t addr) {
    asm volatile("ldmatrix.sync.aligned.m8n8.x4.shared.b16 {%0,%1,%2,%3}, [%4];"
                 : "=r"(r[0]), "=r"(r[1]), "=r"(r[2]), "=r"(r[3]) : "r"(addr));
}
__device__ __forceinline__ void ldsm_x2(uint32_t* r, uint32_t addr) {
    asm volatile("ldmatrix.sync.aligned.m8n8.x2.shared.b16 {%0,%1}, [%2];"
                 : "=r"(r[0]), "=r"(r[1]) : "r"(addr));
}
__device__ __forceinline__ void mma_bf16(float* c, const uint32_t* a, const uint32_t* b) {
    asm volatile("mma.sync.aligned.m16n8k16.row.col.f32.bf16.bf16.f32 "
                 "{%0,%1,%2,%3}, {%4,%5,%6,%7}, {%8,%9}, {%0,%1,%2,%3};"
                 : "+f"(c[0]), "+f"(c[1]), "+f"(c[2]), "+f"(c[3])
                 : "r"(a[0]), "r"(a[1]), "r"(a[2]), "r"(a[3]), "r"(b[0]), "r"(b[1]));
}
__device__ __forceinline__ void mma_f16(float* c, const uint32_t* a, const uint32_t* b) {
    asm volatile("mma.sync.aligned.m16n8k16.row.col.f32.f16.f16.f32 "
                 "{%0,%1,%2,%3}, {%4,%5,%6,%7}, {%8,%9}, {%0,%1,%2,%3};"
                 : "+f"(c[0]), "+f"(c[1]), "+f"(c[2]), "+f"(c[3])
                 : "r"(a[0]), "r"(a[1]), "r"(a[2]), "r"(a[3]), "r"(b[0]), "r"(b[1]));
}
typedef unsigned long long ull;
__device__ __forceinline__ ull pk2(float lo, float hi) {
    ull r; asm("mov.b64 %0, {%1, %2};" : "=l"(r) : "f"(lo), "f"(hi)); return r;
}
__device__ __forceinline__ void upk2(float& lo, float& hi, ull v) {
    asm("mov.b64 {%0, %1}, %2;" : "=f"(lo), "=f"(hi) : "l"(v));
}
__device__ __forceinline__ ull fma2(ull a, ull b, ull c) {
    ull d; asm("fma.rn.f32x2 %0, %1, %2, %3;" : "=l"(d) : "l"(a), "l"(b), "l"(c)); return d;
}
__device__ __forceinline__ ull mul2(ull a, ull b) {
    ull d; asm("mul.rn.f32x2 %0, %1, %2;" : "=l"(d) : "l"(a), "l"(b)); return d;
}

// ---------------- conversion kernels ----------------
__global__ void rowconv_kernel(const float* __restrict__ src,
                               __nv_bfloat16* __restrict__ hi,
                               __nv_bfloat16* __restrict__ lo, int n)
{
    int i = blockIdx.x * blockDim.x + threadIdx.x;
    if (i * 4 >= n) return;
    float4 v = *(const float4*)(src + i * 4);
    float vv[4] = {v.x, v.y, v.z, v.w};
#pragma unroll
    for (int j = 0; j < 4; j++) {
        __nv_bfloat16 h = __float2bfloat16(vv[j]);
        hi[i * 4 + j] = h;
        lo[i * 4 + j] = __float2bfloat16(vv[j] - __bfloat162float(h));
    }
}

// W [K,N] fp32 -> T [N,K] bf16 hi/lo
__global__ void transconv_kernel(const float* __restrict__ W,
                                 __nv_bfloat16* __restrict__ Thi,
                                 __nv_bfloat16* __restrict__ Tlo, int K, int N)
{
    __shared__ float s[32][33];
    int tx = threadIdx.x, ty = threadIdx.y;
    int n0 = blockIdx.x * 32, k0 = blockIdx.y * 32;
#pragma unroll
    for (int i = 0; i < 4; i++)
        s[ty + i * 8][tx] = W[(size_t)(k0 + ty + i * 8) * N + n0 + tx];
    __syncthreads();
#pragma unroll
    for (int i = 0; i < 4; i++) {
        int n = n0 + ty + i * 8, k = k0 + tx;
        float v = s[tx][ty + i * 8];
        __nv_bfloat16 h = __float2bfloat16(v);
        Thi[(size_t)n * K + k] = h;
        Tlo[(size_t)n * K + k] = __float2bfloat16(v - __bfloat162float(h));
    }
}

// W [K,N] fp32 -> T [N,K] single fp16 scaled by 32
__global__ void transconv_h_kernel(const float* __restrict__ W,
                                   __half* __restrict__ Th, int K, int N)
{
    __shared__ float s[32][33];
    int tx = threadIdx.x, ty = threadIdx.y;
    int n0 = blockIdx.x * 32, k0 = blockIdx.y * 32;
#pragma unroll
    for (int i = 0; i < 4; i++)
        s[ty + i * 8][tx] = W[(size_t)(k0 + ty + i * 8) * N + n0 + tx];
    __syncthreads();
#pragma unroll
    for (int i = 0; i < 4; i++) {
        int n = n0 + ty + i * 8, k = k0 + tx;
        Th[(size_t)n * K + k] = __float2half_rn(s[tx][ty + i * 8] * WSCALE);
    }
}

// ---------------- shared tile geometry ----------------
#define ROWB      80
#define TILE_B    (128 * ROWB)
#define BUF_B4    (4 * TILE_B)
#define SMEM_BF16 (2 * BUF_B4)             // 81920
#define BUF_B3    (3 * TILE_B)
#define SMEM_F16  (2 * BUF_B3)             // 61440

// ---------------- bf16 split x3 GEMM (gemm1, gemm_yo) ----------------
// supports split-K via blockIdx.z (chunk offset z*KCHUNKS, output offset z*M*N)
template<int KCHUNKS, bool RELU, bool BIAS, bool HILO>
__global__ __launch_bounds__(256, 2)
void mma_gemm(const __nv_bfloat16* __restrict__ Ahi, const __nv_bfloat16* __restrict__ Alo,
              const __nv_bfloat16* __restrict__ Bhi, const __nv_bfloat16* __restrict__ Blo,
              const float* __restrict__ bias,
              float* __restrict__ Cout,
              __half* __restrict__ Chi, __half* __restrict__ Clo,
              int M, int N, int K)
{
    extern __shared__ char smem[];
    const uint32_t sbase = smem_u32(smem);
    const int tid  = threadIdx.x;
    const int lane = tid & 31, wid = tid >> 5;
    const int warp_m = wid >> 2;
    const int warp_n = wid & 3;
    const int bn = blockIdx.x * 128;
    const int bm = blockIdx.y * 128;
    const int zoff = blockIdx.z * KCHUNKS;
    Cout += (size_t)blockIdx.z * M * N;

    const __nv_bfloat16* srcs[4] = {Ahi, Alo, Bhi, Blo};

    auto load_chunk = [&](int gc, int buf) {
#pragma unroll
        for (int w = 0; w < 4; w++) {
            const int rowbase = (w < 2) ? bm : bn;
            const __nv_bfloat16* src = srcs[w];
#pragma unroll
            for (int t = 0; t < 2; t++) {
                int idx = tid + t * 256;
                int row = idx >> 2, seg = idx & 3;
                char* dst = smem + buf * BUF_B4 + w * TILE_B + row * ROWB + seg * 16;
                const char* s = (const char*)src +
                    ((size_t)(rowbase + row) * K + (size_t)gc * 32) * 2 + seg * 16;
                __pipeline_memcpy_async(dst, s, 16);
            }
        }
    };

    float acc[4][4][4];
#pragma unroll
    for (int i = 0; i < 4; i++)
#pragma unroll
        for (int j = 0; j < 4; j++)
#pragma unroll
            for (int q = 0; q < 4; q++) acc[i][j][q] = 0.f;

    load_chunk(zoff, 0);
    __pipeline_commit();
    __pipeline_wait_prior(0);
    __syncthreads();

    const uint32_t a_lane_off = (uint32_t)((lane & 15) * ROWB + (lane >> 4) * 16);
    const uint32_t b_lane_off = (uint32_t)((lane & 7) * ROWB + ((lane >> 3) & 1) * 16);

    for (int c = 0; c < KCHUNKS; c++) {
        if (c + 1 < KCHUNKS) { load_chunk(zoff + c + 1, (c + 1) & 1); __pipeline_commit(); }

        const uint32_t bufb = sbase + (c & 1) * BUF_B4;
#pragma unroll
        for (int s = 0; s < 2; s++) {
            uint32_t ah[4][4], al[4][4];
            const uint32_t ks = s * 32;
#pragma unroll
            for (int i = 0; i < 4; i++) {
                uint32_t ro = (uint32_t)((warp_m * 64 + i * 16) * ROWB) + ks + a_lane_off;
                ldsm_x4(ah[i], bufb + 0 * TILE_B + ro);
                ldsm_x4(al[i], bufb + 1 * TILE_B + ro);
            }
#pragma unroll
            for (int j = 0; j < 4; j++) {
                uint32_t bh[2], bl[2];
                uint32_t ro = (uint32_t)((warp_n * 32 + j * 8) * ROWB) + ks + b_lane_off;
                ldsm_x2(bh, bufb + 2 * TILE_B + ro);
                ldsm_x2(bl, bufb + 3 * TILE_B + ro);
#pragma unroll
                for (int i = 0; i < 4; i++) {
                    mma_bf16(acc[i][j], ah[i], bh);
                    mma_bf16(acc[i][j], ah[i], bl);
                    mma_bf16(acc[i][j], al[i], bh);
                }
            }
        }
        if (c + 1 < KCHUNKS) __pipeline_wait_prior(0);
        __syncthreads();
    }

    const int r0 = lane >> 2;
    const int q0 = (lane & 3) * 2;
#pragma unroll
    for (int j = 0; j < 4; j++) {
        const int n0 = bn + warp_n * 32 + j * 8 + q0;
        float b0 = BIAS ? bias[n0] : 0.f;
        float b1 = BIAS ? bias[n0 + 1] : 0.f;
#pragma unroll
        for (int i = 0; i < 4; i++) {
            const int m0 = bm + warp_m * 64 + i * 16 + r0;
            float v0 = acc[i][j][0] + b0, v1 = acc[i][j][1] + b1;
            float v2 = acc[i][j][2] + b0, v3 = acc[i][j][3] + b1;
            if (RELU) { v0 = fmaxf(v0, 0.f); v1 = fmaxf(v1, 0.f);
                        v2 = fmaxf(v2, 0.f); v3 = fmaxf(v3, 0.f); }
            *(float2*)&Cout[(size_t)m0 * N + n0]       = make_float2(v0, v1);
            *(float2*)&Cout[(size_t)(m0 + 8) * N + n0] = make_float2(v2, v3);
            if (HILO) {   // write fp16 hi/lo split of the result (for fp16 GEMMs)
                __half h0 = __float2half_rn(v0), h1 = __float2half_rn(v1);
                __half h2 = __float2half_rn(v2), h3 = __float2half_rn(v3);
                __half2 hp0 = {h0, h1}, hp1 = {h2, h3};
                __half2 lp0 = {__float2half_rn(v0 - __half2float(h0)),
                               __float2half_rn(v1 - __half2float(h1))};
                __half2 lp1 = {__float2half_rn(v2 - __half2float(h2)),
                               __float2half_rn(v3 - __half2float(h3))};
                *(__half2*)&Chi[(size_t)m0 * N + n0]       = hp0;
                *(__half2*)&Chi[(size_t)(m0 + 8) * N + n0] = hp1;
                *(__half2*)&Clo[(size_t)m0 * N + n0]       = lp0;
                *(__half2*)&Clo[(size_t)(m0 + 8) * N + n0] = lp1;
            }
        }
    }
}

// ---------------- fp16 2-pass GEMM (B/C projections) ----------------
// C[M,N] = ((Ahi+Alo)[M,K] @ W[N,K]^T) * (1/32); A split exact, W fp16 x32.
template<int KCHUNKS>
__global__ __launch_bounds__(256, 2)
void mma_gemm_h2(const __half* __restrict__ Ahi, const __half* __restrict__ Alo,
                 const __half* __restrict__ Wm,
                 float* __restrict__ Cout, int M, int N, int K)
{
    extern __shared__ char smem[];
    const uint32_t sbase = smem_u32(smem);
    const int tid  = threadIdx.x;
    const int lane = tid & 31, wid = tid >> 5;
    const int warp_m = wid >> 2;
    const int warp_n = wid & 3;
    const int bn = blockIdx.x * 128;
    const int bm = blockIdx.y * 128;

    const __half* srcs[3] = {Ahi, Alo, Wm};

    auto load_chunk = [&](int c, int buf) {
#pragma unroll
        for (int w = 0; w < 3; w++) {
            const int rowbase = (w < 2) ? bm : bn;
            const __half* src = srcs[w];
#pragma unroll
            for (int t = 0; t < 2; t++) {
                int idx = tid + t * 256;
                int row = idx >> 2, seg = idx & 3;
                char* dst = smem + buf * BUF_B3 + w * TILE_B + row * ROWB + seg * 16;
                const char* s = (const char*)src +
                    ((size_t)(rowbase + row) * K + (size_t)c * 32) * 2 + seg * 16;
                __pipeline_memcpy_async(dst, s, 16);
            }
        }
    };

    float acc[4][4][4];
#pragma unroll
    for (int i = 0; i < 4; i++)
#pragma unroll
        for (int j = 0; j < 4; j++)
#pragma unroll
            for (int q = 0; q < 4; q++) acc[i][j][q] = 0.f;

    load_chunk(0, 0);
    __pipeline_commit();
    __pipeline_wait_prior(0);
    __syncthreads();

    const uint32_t a_lane_off = (uint32_t)((lane & 15) * ROWB + (lane >> 4) * 16);
    const uint32_t b_lane_off = (uint32_t)((lane & 7) * ROWB + ((lane >> 3) & 1) * 16);

    for (int c = 0; c < KCHUNKS; c++) {
        if (c + 1 < KCHUNKS) { load_chunk(c + 1, (c + 1) & 1); __pipeline_commit(); }

        const uint32_t bufb = sbase + (c & 1) * BUF_B3;
#pragma unroll
        for (int s = 0; s < 2; s++) {
            uint32_t ah[4][4], al[4][4];
            const uint32_t ks = s * 32;
#pragma unroll
            for (int i = 0; i < 4; i++) {
                uint32_t ro = (uint32_t)((warp_m * 64 + i * 16) * ROWB) + ks + a_lane_off;
                ldsm_x4(ah[i], bufb + 0 * TILE_B + ro);
                ldsm_x4(al[i], bufb + 1 * TILE_B + ro);
            }
#pragma unroll
            for (int j = 0; j < 4; j++) {
                uint32_t wf[2];
                uint32_t ro = (uint32_t)((warp_n * 32 + j * 8) * ROWB) + ks + b_lane_off;
                ldsm_x2(wf, bufb + 2 * TILE_B + ro);
#pragma unroll
                for (int i = 0; i < 4; i++) {
                    mma_f16(acc[i][j], ah[i], wf);
                    mma_f16(acc[i][j], al[i], wf);
                }
            }
        }
        if (c + 1 < KCHUNKS) __pipeline_wait_prior(0);
        __syncthreads();
    }

    const int r0 = lane >> 2;
    const int q0 = (lane & 3) * 2;
#pragma unroll
    for (int j = 0; j < 4; j++) {
        const int n0 = bn + warp_n * 32 + j * 8 + q0;
#pragma unroll
        for (int i = 0; i < 4; i++) {
            const int m0 = bm + warp_m * 64 + i * 16 + r0;
            *(float2*)&Cout[(size_t)m0 * N + n0] =
                make_float2(acc[i][j][0] * WISCALE, acc[i][j][1] * WISCALE);
            *(float2*)&Cout[(size_t)(m0 + 8) * N + n0] =
                make_float2(acc[i][j][2] * WISCALE, acc[i][j][3] * WISCALE);
        }
    }
}

// ---------------- dt projection + softplus + decay ----------------
__global__ __launch_bounds__(256)
void dtdecay_kernel(const float* __restrict__ X, const float* __restrict__ W_dt,
                    const float* __restrict__ dt_bias, const float* __restrict__ A_log,
                    float* __restrict__ dts, float* __restrict__ decs)
{
    __shared__ float Xs[16][64];
    __shared__ float Ws[64][16];
    const int tid = threadIdx.x;
    const int m0  = blockIdx.x * 16;
    const int h   = tid & 15;
    const int mi  = tid >> 4;

    float acc = 0.f;
    for (int k0 = 0; k0 < D_IN; k0 += 64) {
        __syncthreads();
        *(float4*)&Xs[tid >> 4][(tid & 15) * 4] =
            *(const float4*)&X[(size_t)(m0 + (tid >> 4)) * D_IN + k0 + (tid & 15) * 4];
        *(float4*)&Ws[tid >> 2][(tid & 3) * 4] =
            *(const float4*)&W_dt[(size_t)(k0 + (tid >> 2)) * NHEAD + (tid & 3) * 4];
        __syncthreads();
#pragma unroll
        for (int k = 0; k < 64; k++)
            acc = fmaf(Xs[mi][k], Ws[k][h], acc);
    }
    const int m = m0 + mi;
    float v  = acc + dt_bias[h];
    float dt = (v > 20.f) ? v : log1pf(expf(v));
    float A  = expf(A_log[h]);
    dts[m * NHEAD + h]  = dt;
    decs[m * NHEAD + h] = expf(-A * dt);
}

// ---------------- selective scan (packed f32x2 state) ----------------
__global__ __launch_bounds__(128, 1)
void scan_kernel(const float* __restrict__ X, const float* __restrict__ Bm,
                 const float* __restrict__ Cm, const float* __restrict__ dts,
                 const float* __restrict__ decs,
                 __nv_bfloat16* __restrict__ Yhi, __nv_bfloat16* __restrict__ Ylo)
{
    const int bh = blockIdx.x;
    const int b  = bh >> 4;
    const int h  = bh & 15;
    const int tid = threadIdx.x;

    __shared__ __align__(16) float xb[4][PHEAD];
    __shared__ __align__(16) float Bb[4][NSTATE];
    __shared__ __align__(16) float Cb[4][NSTATE];
    __shared__ float sc[4][2];

    ull hs2[32];
#pragma unroll
    for (int i = 0; i < 32; i++) hs2[i] = 0ull;

    auto issue = [&](int t) {
        const int st = t & 3;
        const size_t m = (size_t)t * BSZ + b;
        __pipeline_memcpy_async(&xb[st][tid], X + m * D_IN + h * PHEAD + tid, 4);
        if (tid < 64)
            __pipeline_memcpy_async(&Bb[st][tid], Bm + m * HN + h * NSTATE + tid, 4);
        else
            __pipeline_memcpy_async(&Cb[st][tid - 64], Cm + m * HN + h * NSTATE + (tid - 64), 4);
        if (tid == 0) __pipeline_memcpy_async(&sc[st][0], dts  + m * NHEAD + h, 4);
        if (tid == 1) __pipeline_memcpy_async(&sc[st][1], decs + m * NHEAD + h, 4);
    };

    issue(0); __pipeline_commit();
    issue(1); __pipeline_commit();
    issue(2); __pipeline_commit();

    for (int t = 0; t < T_LEN; t++) {
        const int st = t & 3;
        __pipeline_wait_prior(2);
        __syncthreads();
        if (t + 3 < T_LEN) issue(t + 3);
        __pipeline_commit();

        const float dtv = sc[st][0];
        const float dec = sc[st][1];
        const float cc  = dtv * xb[st][tid];
        const ull dec2 = pk2(dec, dec);
        const ull cc2  = pk2(cc, cc);

        const longlong2* B2 = (const longlong2*)Bb[st];
        const longlong2* C2 = (const longlong2*)Cb[st];
        ull ya = 0ull, yb = 0ull;
#pragma unroll
        for (int j = 0; j < 16; j++) {
            longlong2 bv = B2[j];
            longlong2 cv = C2[j];
            hs2[2*j]   = fma2(dec2, hs2[2*j],   mul2(cc2, (ull)bv.x));
            ya         = fma2(hs2[2*j],   (ull)cv.x, ya);
            hs2[2*j+1] = fma2(dec2, hs2[2*j+1], mul2(cc2, (ull)bv.y));
            yb         = fma2(hs2[2*j+1], (ull)cv.y, yb);
        }
        float a0, a1, c0, c1;
        upk2(a0, a1, ya);
        upk2(c0, c1, yb);
        const float y = (a0 + a1) + (c0 + c1);

        const size_t m = (size_t)t * BSZ + b;
        __nv_bfloat16 hy = __float2bfloat16(y);
        Yhi[m * D_IN + h * PHEAD + tid] = hy;
        Ylo[m * D_IN + h * PHEAD + tid] = __float2bfloat16(y - __bfloat162float(hy));
    }
}

// ---------------- policy head (fuses split-K sum + bias + relu) ------------
__global__ __launch_bounds__(256)
void head_kernel(const float* __restrict__ Zp, const float* __restrict__ b_yo,
                 const float* __restrict__ Wh, const float* __restrict__ bh,
                 float* __restrict__ out)
{
    __shared__ float Zs[4][NUNITS];
    __shared__ float Ws[64][NACT];
    const int tid = threadIdx.x;
    const int m0  = blockIdx.x * 4;
    const int n   = tid & 63;
    const int mi  = tid >> 6;

    {
        const int r  = tid >> 6;
        const int c4 = (tid & 63) * 4;
        float4 z0 = *(const float4*)&Zp[(size_t)(m0 + r) * NUNITS + c4];
        float4 z1 = *(const float4*)&Zp[(size_t)M_TOT * NUNITS + (size_t)(m0 + r) * NUNITS + c4];
        float4 by = *(const float4*)&b_yo[c4];
        float4 v;
        v.x = fmaxf(z0.x + z1.x + by.x, 0.f);
        v.y = fmaxf(z0.y + z1.y + by.y, 0.f);
        v.z = fmaxf(z0.z + z1.z + by.z, 0.f);
        v.w = fmaxf(z0.w + z1.w + by.w, 0.f);
        *(float4*)&Zs[r][c4] = v;
    }

    float acc = bh[n];
    for (int k0 = 0; k0 < NUNITS; k0 += 64) {
        __syncthreads();
#pragma unroll
        for (int j = 0; j < 4; j++) {
            int idx = tid + j * 256;
            int r = idx >> 4, c4 = (idx & 15) * 4;
            *(float4*)&Ws[r][c4] = *(const float4*)&Wh[(size_t)(k0 + r) * NACT + c4];
        }
        __syncthreads();
#pragma unroll
        for (int k = 0; k < 64; k++)
            acc = fmaf(Zs[mi][k0 + k], Ws[k][n], acc);
    }
    out[(size_t)(m0 + mi) * NACT + n] = acc;
}

// ---------------- launch ----------------
extern "C" void kernel_launch(void* const* d_in, const int* in_sizes, int n_in,
                              void* d_out, int out_size)
{
    const float* obs     = (const float*)d_in[0];
    const float* W_in    = (const float*)d_in[1];
    const float* b_in    = (const float*)d_in[2];
    const float* A_log   = (const float*)d_in[3];
    const float* dt_bias = (const float*)d_in[4];
    const float* W_dt    = (const float*)d_in[5];
    const float* W_B     = (const float*)d_in[6];
    const float* W_C     = (const float*)d_in[7];
    const float* W_yo    = (const float*)d_in[8];
    const float* b_yo    = (const float*)d_in[9];
    const float* W_head  = (const float*)d_in[10];
    const float* b_head  = (const float*)d_in[11];
    float* out = (float*)d_out;

    float *X, *Bmp, *Cmp, *dts, *dec, *Zp;
    __half *Xhi, *Xlo, *WBh, *WCh;
    __nv_bfloat16 *Yhi, *Ylo, *obsh, *obsl, *Winh, *Winl, *Wyoh, *Wyol;
    cudaGetSymbolAddress((void**)&X,    g_X);
    cudaGetSymbolAddress((void**)&Xhi,  g_Xhi);
    cudaGetSymbolAddress((void**)&Xlo,  g_Xlo);
    cudaGetSymbolAddress((void**)&Bmp,  g_Bm);
    cudaGetSymbolAddress((void**)&Cmp,  g_Cm);
    cudaGetSymbolAddress((void**)&dts,  g_dt);
    cudaGetSymbolAddress((void**)&dec,  g_dec);
    cudaGetSymbolAddress((void**)&Yhi,  g_Yhi);
    cudaGetSymbolAddress((void**)&Ylo,  g_Ylo);
    cudaGetSymbolAddress((void**)&Zp,   g_Zp);
    cudaGetSymbolAddress((void**)&obsh, g_obs_hi);
    cudaGetSymbolAddress((void**)&obsl, g_obs_lo);
    cudaGetSymbolAddress((void**)&Winh, g_Win_hi);
    cudaGetSymbolAddress((void**)&Winl, g_Win_lo);
    cudaGetSymbolAddress((void**)&WBh,  g_WB_h);
    cudaGetSymbolAddress((void**)&WCh,  g_WC_h);
    cudaGetSymbolAddress((void**)&Wyoh, g_Wyo_hi);
    cudaGetSymbolAddress((void**)&Wyol, g_Wyo_lo);

    static cudaStream_t sB = nullptr, sC = nullptr;
    static cudaEvent_t eFork, eWB, eWC, eWyo, eX, eC, eD;
    if (!sB) {
        cudaStreamCreateWithFlags(&sB, cudaStreamNonBlocking);
        cudaStreamCreateWithFlags(&sC, cudaStreamNonBlocking);
        cudaEventCreateWithFlags(&eFork, cudaEventDisableTiming);
        cudaEventCreateWithFlags(&eWB,  cudaEventDisableTiming);
        cudaEventCreateWithFlags(&eWC,  cudaEventDisableTiming);
        cudaEventCreateWithFlags(&eWyo, cudaEventDisableTiming);
        cudaEventCreateWithFlags(&eX,   cudaEventDisableTiming);
        cudaEventCreateWithFlags(&eC,   cudaEventDisableTiming);
        cudaEventCreateWithFlags(&eD,   cudaEventDisableTiming);

        cudaFuncSetAttribute(mma_gemm<8,  true,  true,  true >, cudaFuncAttributeMaxDynamicSharedMemorySize, SMEM_BF16);
        cudaFuncSetAttribute(mma_gemm<32, false, false, false>, cudaFuncAttributeMaxDynamicSharedMemorySize, SMEM_BF16);
        cudaFuncSetAttribute(mma_gemm_h2<64>, cudaFuncAttributeMaxDynamicSharedMemorySize, SMEM_F16);
    }

    cudaEventRecord(eFork, 0);
    cudaStreamWaitEvent(sB, eFork, 0);
    cudaStreamWaitEvent(sC, eFork, 0);

    // side streams: weight conversions
    transconv_h_kernel<<<dim3(HN / 32, D_IN / 32), dim3(32, 8), 0, sB>>>(W_B, WBh, D_IN, HN);
    cudaEventRecord(eWB, sB);
    transconv_h_kernel<<<dim3(HN / 32, D_IN / 32), dim3(32, 8), 0, sC>>>(W_C, WCh, D_IN, HN);
    cudaEventRecord(eWC, sC);
    transconv_kernel<<<dim3(NUNITS / 32, D_IN / 32), dim3(32, 8), 0, sC>>>(W_yo, Wyoh, Wyol, D_IN, NUNITS);
    cudaEventRecord(eWyo, sC);

    // main: obs conv, Win conv, GEMM1 (bf16x3) -> X fp32 + fp16 hi/lo
    rowconv_kernel<<<(M_TOT * OBS_DIM / 4 + 255) / 256, 256>>>(obs, obsh, obsl, M_TOT * OBS_DIM);
    transconv_kernel<<<dim3(D_IN / 32, OBS_DIM / 32), dim3(32, 8)>>>(W_in, Winh, Winl, OBS_DIM, D_IN);
    mma_gemm<8, true, true, true><<<dim3(D_IN / 128, M_TOT / 128, 1), 256, SMEM_BF16>>>(
        obsh, obsl, Winh, Winl, b_in, X, Xhi, Xlo, M_TOT, D_IN, OBS_DIM);
    cudaEventRecord(eX, 0);

    // B projection (fp16 2-pass) on main
    cudaStreamWaitEvent(0, eWB, 0);
    mma_gemm_h2<64><<<dim3(HN / 128, M_TOT / 128), 256, SMEM_F16>>>(
        Xhi, Xlo, WBh, Bmp, M_TOT, HN, D_IN);

    // C projection on stream B
    cudaStreamWaitEvent(sB, eX, 0);
    cudaStreamWaitEvent(sB, eWC, 0);
    mma_gemm_h2<64><<<dim3(HN / 128, M_TOT / 128), 256, SMEM_F16, sB>>>(
        Xhi, Xlo, WCh, Cmp, M_TOT, HN, D_IN);
    cudaEventRecord(eC, sB);

    // dt/decay on stream C
    cudaStreamWaitEvent(sC, eX, 0);
    dtdecay_kernel<<<M_TOT / 16, 256, 0, sC>>>(X, W_dt, dt_bias, A_log, dts, dec);
    cudaEventRecord(eD, sC);

    // join -> scan
    cudaStreamWaitEvent(0, eC, 0);
    cudaStreamWaitEvent(0, eD, 0);
    scan_kernel<<<BSZ * NHEAD, 128>>>(X, Bmp, Cmp, dts, dec, Yhi, Ylo);

    // output projection (bf16x3, split-K=2) + head
    cudaStreamWaitEvent(0, eWyo, 0);
    mma_gemm<32, false, false, false><<<dim3(NUNITS / 128, M_TOT / 128, 2), 256, SMEM_BF16>>>(
        Yhi, Ylo, Wyoh, Wyol, nullptr, Zp, nullptr, nullptr, M_TOT, NUNITS, D_IN);
    head_kernel<<<M_TOT / 4, 256>>>(Zp, b_yo, W_head, b_head, out);
}

// round 7
// speedup vs baseline: 6.5909x; 1.2213x over previous
#include <cuda_runtime.h>
#include <cuda_pipeline.h>
#include <cuda_bf16.h>
#include <cuda_fp16.h>
#include <math.h>
#include <stdint.h>

// ---------------- problem dims ----------------
#define T_LEN   512
#define BSZ     8
#define M_TOT   (T_LEN * BSZ)      // 4096
#define OBS_DIM 256
#define D_IN    2048
#define NHEAD   16
#define NSTATE  64
#define PHEAD   128
#define NUNITS  256
#define NACT    64
#define HN      (NHEAD * NSTATE)    // 1024
#define WSCALE  32.0f
#define WISCALE (1.0f / 32.0f)

// ---------------- scratch ----------------
__device__ float          g_X   [M_TOT * D_IN];
__device__ __half         g_Xh  [M_TOT * D_IN];      // single fp16 of X
__device__ float          g_Bm  [M_TOT * HN];
__device__ float          g_Cm  [M_TOT * HN];
__device__ float          g_dt  [M_TOT * NHEAD];
__device__ float          g_dec [M_TOT * NHEAD];
__device__ __half         g_Yhi [M_TOT * D_IN];      // fp16 hi of Y
__device__ __half         g_Ylo [M_TOT * D_IN];      // fp16 lo of Y
__device__ float          g_Zp  [2 * M_TOT * NUNITS];  // split-K partials
__device__ __nv_bfloat16  g_obs_hi[M_TOT * OBS_DIM];
__device__ __nv_bfloat16  g_obs_lo[M_TOT * OBS_DIM];
__device__ __nv_bfloat16  g_Win_hi[D_IN * OBS_DIM];
__device__ __nv_bfloat16  g_Win_lo[D_IN * OBS_DIM];
__device__ __half         g_WB_h [HN * D_IN];          // fp16 x32
__device__ __half         g_WC_h [HN * D_IN];
__device__ __half         g_Wyo_h[NUNITS * D_IN];      // fp16 x32

// ---------------- helpers ----------------
__device__ __forceinline__ uint32_t smem_u32(const void* p) {
    uint32_t a;
    asm("{ .reg .u64 t; cvta.to.shared.u64 t, %1; cvt.u32.u64 %0, t; }" : "=r"(a) : "l"(p));
    return a;
}
__device__ __forceinline__ void ldsm_x4(uint32_t* r, uint32_t addr) {
    asm volatile("ldmatrix.sync.aligned.m8n8.x4.shared.b16 {%0,%1,%2,%3}, [%4];"
                 : "=r"(r[0]), "=r"(r[1]), "=r"(r[2]), "=r"(r[3]) : "r"(addr));
}
__device__ __forceinline__ void ldsm_x2(uint32_t* r, uint32_t addr) {
    asm volatile("ldmatrix.sync.aligned.m8n8.x2.shared.b16 {%0,%1}, [%2];"
                 : "=r"(r[0]), "=r"(r[1]) : "r"(addr));
}
__device__ __forceinline__ void mma_bf16(float* c, const uint32_t* a, const uint32_t* b) {
    asm volatile("mma.sync.aligned.m16n8k16.row.col.f32.bf16.bf16.f32 "
                 "{%0,%1,%2,%3}, {%4,%5,%6,%7}, {%8,%9}, {%0,%1,%2,%3};"
                 : "+f"(c[0]), "+f"(c[1]), "+f"(c[2]), "+f"(c[3])
                 : "r"(a[0]), "r"(a[1]), "r"(a[2]), "r"(a[3]), "r"(b[0]), "r"(b[1]));
}
__device__ __forceinline__ void mma_f16(float* c, const uint32_t* a, const uint32_t* b) {
    asm volatile("mma.sync.aligned.m16n8k16.row.col.f32.f16.f16.f32 "
                 "{%0,%1,%2,%3}, {%4,%5,%6,%7}, {%8,%9}, {%0,%1,%2,%3};"
                 : "+f"(c[0]), "+f"(c[1]), "+f"(c[2]), "+f"(c[3])
                 : "r"(a[0]), "r"(a[1]), "r"(a[2]), "r"(a[3]), "r"(b[0]), "r"(b[1]));
}
typedef unsigned long long ull;
__device__ __forceinline__ ull pk2(float lo, float hi) {
    ull r; asm("mov.b64 %0, {%1, %2};" : "=l"(r) : "f"(lo), "f"(hi)); return r;
}
__device__ __forceinline__ void upk2(float& lo, float& hi, ull v) {
    asm("mov.b64 {%0, %1}, %2;" : "=f"(lo), "=f"(hi) : "l"(v));
}
__device__ __forceinline__ ull fma2(ull a, ull b, ull c) {
    ull d; asm("fma.rn.f32x2 %0, %1, %2, %3;" : "=l"(d) : "l"(a), "l"(b), "l"(c)); return d;
}
__device__ __forceinline__ ull mul2(ull a, ull b) {
    ull d; asm("mul.rn.f32x2 %0, %1, %2;" : "=l"(d) : "l"(a), "l"(b)); return d;
}

// ---------------- conversion kernels ----------------
__global__ void rowconv_kernel(const float* __restrict__ src,
                               __nv_bfloat16* __restrict__ hi,
                               __nv_bfloat16* __restrict__ lo, int n)
{
    int i = blockIdx.x * blockDim.x + threadIdx.x;
    if (i * 4 >= n) return;
    float4 v = *(const float4*)(src + i * 4);
    float vv[4] = {v.x, v.y, v.z, v.w};
#pragma unroll
    for (int j = 0; j < 4; j++) {
        __nv_bfloat16 h = __float2bfloat16(vv[j]);
        hi[i * 4 + j] = h;
        lo[i * 4 + j] = __float2bfloat16(vv[j] - __bfloat162float(h));
    }
}

// W [K,N] fp32 -> T [N,K] bf16 hi/lo
__global__ void transconv_kernel(const float* __restrict__ W,
                                 __nv_bfloat16* __restrict__ Thi,
                                 __nv_bfloat16* __restrict__ Tlo, int K, int N)
{
    __shared__ float s[32][33];
    int tx = threadIdx.x, ty = threadIdx.y;
    int n0 = blockIdx.x * 32, k0 = blockIdx.y * 32;
#pragma unroll
    for (int i = 0; i < 4; i++)
        s[ty + i * 8][tx] = W[(size_t)(k0 + ty + i * 8) * N + n0 + tx];
    __syncthreads();
#pragma unroll
    for (int i = 0; i < 4; i++) {
        int n = n0 + ty + i * 8, k = k0 + tx;
        float v = s[tx][ty + i * 8];
        __nv_bfloat16 h = __float2bfloat16(v);
        Thi[(size_t)n * K + k] = h;
        Tlo[(size_t)n * K + k] = __float2bfloat16(v - __bfloat162float(h));
    }
}

// W [K,N] fp32 -> T [N,K] single fp16 scaled by 32
__global__ void transconv_h_kernel(const float* __restrict__ W,
                                   __half* __restrict__ Th, int K, int N)
{
    __shared__ float s[32][33];
    int tx = threadIdx.x, ty = threadIdx.y;
    int n0 = blockIdx.x * 32, k0 = blockIdx.y * 32;
#pragma unroll
    for (int i = 0; i < 4; i++)
        s[ty + i * 8][tx] = W[(size_t)(k0 + ty + i * 8) * N + n0 + tx];
    __syncthreads();
#pragma unroll
    for (int i = 0; i < 4; i++) {
        int n = n0 + ty + i * 8, k = k0 + tx;
        Th[(size_t)n * K + k] = __float2half_rn(s[tx][ty + i * 8] * WSCALE);
    }
}

// ---------------- tile geometry ----------------
#define ROWB      80
#define TILE_B    (128 * ROWB)
#define BUF_B4    (4 * TILE_B)
#define SMEM_BF16 (2 * BUF_B4)             // 81920
#define BUF_B3    (3 * TILE_B)
#define SMEM_F16_3 (2 * BUF_B3)            // 61440
#define BUF_B2    (2 * TILE_B)
#define SMEM_F16_2 (2 * BUF_B2)            // 40960

// ---------------- bf16x3 GEMM (GEMM1 only) ----------------
// epilogue: X fp32, relu, bias, + single fp16 Xh
template<int KCHUNKS>
__global__ __launch_bounds__(256, 2)
void mma_gemm_bf3(const __nv_bfloat16* __restrict__ Ahi, const __nv_bfloat16* __restrict__ Alo,
                  const __nv_bfloat16* __restrict__ Bhi, const __nv_bfloat16* __restrict__ Blo,
                  const float* __restrict__ bias,
                  float* __restrict__ Cout, __half* __restrict__ Ch,
                  int M, int N, int K)
{
    extern __shared__ char smem[];
    const uint32_t sbase = smem_u32(smem);
    const int tid  = threadIdx.x;
    const int lane = tid & 31, wid = tid >> 5;
    const int warp_m = wid >> 2;
    const int warp_n = wid & 3;
    const int bn = blockIdx.x * 128;
    const int bm = blockIdx.y * 128;

    const __nv_bfloat16* srcs[4] = {Ahi, Alo, Bhi, Blo};

    auto load_chunk = [&](int c, int buf) {
#pragma unroll
        for (int w = 0; w < 4; w++) {
            const int rowbase = (w < 2) ? bm : bn;
            const __nv_bfloat16* src = srcs[w];
#pragma unroll
            for (int t = 0; t < 2; t++) {
                int idx = tid + t * 256;
                int row = idx >> 2, seg = idx & 3;
                char* dst = smem + buf * BUF_B4 + w * TILE_B + row * ROWB + seg * 16;
                const char* s = (const char*)src +
                    ((size_t)(rowbase + row) * K + (size_t)c * 32) * 2 + seg * 16;
                __pipeline_memcpy_async(dst, s, 16);
            }
        }
    };

    float acc[4][4][4];
#pragma unroll
    for (int i = 0; i < 4; i++)
#pragma unroll
        for (int j = 0; j < 4; j++)
#pragma unroll
            for (int q = 0; q < 4; q++) acc[i][j][q] = 0.f;

    load_chunk(0, 0);
    __pipeline_commit();
    __pipeline_wait_prior(0);
    __syncthreads();

    const uint32_t a_lane_off = (uint32_t)((lane & 15) * ROWB + (lane >> 4) * 16);
    const uint32_t b_lane_off = (uint32_t)((lane & 7) * ROWB + ((lane >> 3) & 1) * 16);

    for (int c = 0; c < KCHUNKS; c++) {
        if (c + 1 < KCHUNKS) { load_chunk(c + 1, (c + 1) & 1); __pipeline_commit(); }
        const uint32_t bufb = sbase + (c & 1) * BUF_B4;
#pragma unroll
        for (int s = 0; s < 2; s++) {
            uint32_t ah[4][4], al[4][4];
            const uint32_t ks = s * 32;
#pragma unroll
            for (int i = 0; i < 4; i++) {
                uint32_t ro = (uint32_t)((warp_m * 64 + i * 16) * ROWB) + ks + a_lane_off;
                ldsm_x4(ah[i], bufb + 0 * TILE_B + ro);
                ldsm_x4(al[i], bufb + 1 * TILE_B + ro);
            }
#pragma unroll
            for (int j = 0; j < 4; j++) {
                uint32_t bh[2], bl[2];
                uint32_t ro = (uint32_t)((warp_n * 32 + j * 8) * ROWB) + ks + b_lane_off;
                ldsm_x2(bh, bufb + 2 * TILE_B + ro);
                ldsm_x2(bl, bufb + 3 * TILE_B + ro);
#pragma unroll
                for (int i = 0; i < 4; i++) {
                    mma_bf16(acc[i][j], ah[i], bh);
                    mma_bf16(acc[i][j], ah[i], bl);
                    mma_bf16(acc[i][j], al[i], bh);
                }
            }
        }
        if (c + 1 < KCHUNKS) __pipeline_wait_prior(0);
        __syncthreads();
    }

    const int r0 = lane >> 2;
    const int q0 = (lane & 3) * 2;
#pragma unroll
    for (int j = 0; j < 4; j++) {
        const int n0 = bn + warp_n * 32 + j * 8 + q0;
        float b0 = bias[n0], b1 = bias[n0 + 1];
#pragma unroll
        for (int i = 0; i < 4; i++) {
            const int m0 = bm + warp_m * 64 + i * 16 + r0;
            float v0 = fmaxf(acc[i][j][0] + b0, 0.f);
            float v1 = fmaxf(acc[i][j][1] + b1, 0.f);
            float v2 = fmaxf(acc[i][j][2] + b0, 0.f);
            float v3 = fmaxf(acc[i][j][3] + b1, 0.f);
            *(float2*)&Cout[(size_t)m0 * N + n0]       = make_float2(v0, v1);
            *(float2*)&Cout[(size_t)(m0 + 8) * N + n0] = make_float2(v2, v3);
            __half2 hp0 = {__float2half_rn(v0), __float2half_rn(v1)};
            __half2 hp1 = {__float2half_rn(v2), __float2half_rn(v3)};
            *(__half2*)&Ch[(size_t)m0 * N + n0]       = hp0;
            *(__half2*)&Ch[(size_t)(m0 + 8) * N + n0] = hp1;
        }
    }
}

// ---------------- fp16 single-pass GEMM (B/C projections) ----------------
template<int KCHUNKS>
__global__ __launch_bounds__(256, 2)
void mma_gemm_h1(const __half* __restrict__ A, const __half* __restrict__ Wm,
                 float* __restrict__ Cout, int M, int N, int K)
{
    extern __shared__ char smem[];
    const uint32_t sbase = smem_u32(smem);
    const int tid  = threadIdx.x;
    const int lane = tid & 31, wid = tid >> 5;
    const int warp_m = wid >> 2;
    const int warp_n = wid & 3;
    const int bn = blockIdx.x * 128;
    const int bm = blockIdx.y * 128;

    const __half* srcs[2] = {A, Wm};

    auto load_chunk = [&](int c, int buf) {
#pragma unroll
        for (int w = 0; w < 2; w++) {
            const int rowbase = (w == 0) ? bm : bn;
            const __half* src = srcs[w];
#pragma unroll
            for (int t = 0; t < 2; t++) {
                int idx = tid + t * 256;
                int row = idx >> 2, seg = idx & 3;
                char* dst = smem + buf * BUF_B2 + w * TILE_B + row * ROWB + seg * 16;
                const char* s = (const char*)src +
                    ((size_t)(rowbase + row) * K + (size_t)c * 32) * 2 + seg * 16;
                __pipeline_memcpy_async(dst, s, 16);
            }
        }
    };

    float acc[4][4][4];
#pragma unroll
    for (int i = 0; i < 4; i++)
#pragma unroll
        for (int j = 0; j < 4; j++)
#pragma unroll
            for (int q = 0; q < 4; q++) acc[i][j][q] = 0.f;

    load_chunk(0, 0);
    __pipeline_commit();
    __pipeline_wait_prior(0);
    __syncthreads();

    const uint32_t a_lane_off = (uint32_t)((lane & 15) * ROWB + (lane >> 4) * 16);
    const uint32_t b_lane_off = (uint32_t)((lane & 7) * ROWB + ((lane >> 3) & 1) * 16);

    for (int c = 0; c < KCHUNKS; c++) {
        if (c + 1 < KCHUNKS) { load_chunk(c + 1, (c + 1) & 1); __pipeline_commit(); }
        const uint32_t bufb = sbase + (c & 1) * BUF_B2;
#pragma unroll
        for (int s = 0; s < 2; s++) {
            uint32_t af[4][4];
            const uint32_t ks = s * 32;
#pragma unroll
            for (int i = 0; i < 4; i++) {
                uint32_t ro = (uint32_t)((warp_m * 64 + i * 16) * ROWB) + ks + a_lane_off;
                ldsm_x4(af[i], bufb + 0 * TILE_B + ro);
            }
#pragma unroll
            for (int j = 0; j < 4; j++) {
                uint32_t wf[2];
                uint32_t ro = (uint32_t)((warp_n * 32 + j * 8) * ROWB) + ks + b_lane_off;
                ldsm_x2(wf, bufb + 1 * TILE_B + ro);
#pragma unroll
                for (int i = 0; i < 4; i++)
                    mma_f16(acc[i][j], af[i], wf);
            }
        }
        if (c + 1 < KCHUNKS) __pipeline_wait_prior(0);
        __syncthreads();
    }

    const int r0 = lane >> 2;
    const int q0 = (lane & 3) * 2;
#pragma unroll
    for (int j = 0; j < 4; j++) {
        const int n0 = bn + warp_n * 32 + j * 8 + q0;
#pragma unroll
        for (int i = 0; i < 4; i++) {
            const int m0 = bm + warp_m * 64 + i * 16 + r0;
            *(float2*)&Cout[(size_t)m0 * N + n0] =
                make_float2(acc[i][j][0] * WISCALE, acc[i][j][1] * WISCALE);
            *(float2*)&Cout[(size_t)(m0 + 8) * N + n0] =
                make_float2(acc[i][j][2] * WISCALE, acc[i][j][3] * WISCALE);
        }
    }
}

// ---------------- fp16 2-pass GEMM (yo projection, split-K) ----------------
template<int KCHUNKS>
__global__ __launch_bounds__(256, 2)
void mma_gemm_h2(const __half* __restrict__ Ahi, const __half* __restrict__ Alo,
                 const __half* __restrict__ Wm,
                 float* __restrict__ Cout, int M, int N, int K)
{
    extern __shared__ char smem[];
    const uint32_t sbase = smem_u32(smem);
    const int tid  = threadIdx.x;
    const int lane = tid & 31, wid = tid >> 5;
    const int warp_m = wid >> 2;
    const int warp_n = wid & 3;
    const int bn = blockIdx.x * 128;
    const int bm = blockIdx.y * 128;
    const int zoff = blockIdx.z * KCHUNKS;
    Cout += (size_t)blockIdx.z * M * N;

    const __half* srcs[3] = {Ahi, Alo, Wm};

    auto load_chunk = [&](int gc, int buf) {
#pragma unroll
        for (int w = 0; w < 3; w++) {
            const int rowbase = (w < 2) ? bm : bn;
            const __half* src = srcs[w];
#pragma unroll
            for (int t = 0; t < 2; t++) {
                int idx = tid + t * 256;
                int row = idx >> 2, seg = idx & 3;
                char* dst = smem + buf * BUF_B3 + w * TILE_B + row * ROWB + seg * 16;
                const char* s = (const char*)src +
                    ((size_t)(rowbase + row) * K + (size_t)gc * 32) * 2 + seg * 16;
                __pipeline_memcpy_async(dst, s, 16);
            }
        }
    };

    float acc[4][4][4];
#pragma unroll
    for (int i = 0; i < 4; i++)
#pragma unroll
        for (int j = 0; j < 4; j++)
#pragma unroll
            for (int q = 0; q < 4; q++) acc[i][j][q] = 0.f;

    load_chunk(zoff, 0);
    __pipeline_commit();
    __pipeline_wait_prior(0);
    __syncthreads();

    const uint32_t a_lane_off = (uint32_t)((lane & 15) * ROWB + (lane >> 4) * 16);
    const uint32_t b_lane_off = (uint32_t)((lane & 7) * ROWB + ((lane >> 3) & 1) * 16);

    for (int c = 0; c < KCHUNKS; c++) {
        if (c + 1 < KCHUNKS) { load_chunk(zoff + c + 1, (c + 1) & 1); __pipeline_commit(); }
        const uint32_t bufb = sbase + (c & 1) * BUF_B3;
#pragma unroll
        for (int s = 0; s < 2; s++) {
            uint32_t ah[4][4], al[4][4];
            const uint32_t ks = s * 32;
#pragma unroll
            for (int i = 0; i < 4; i++) {
                uint32_t ro = (uint32_t)((warp_m * 64 + i * 16) * ROWB) + ks + a_lane_off;
                ldsm_x4(ah[i], bufb + 0 * TILE_B + ro);
                ldsm_x4(al[i], bufb + 1 * TILE_B + ro);
            }
#pragma unroll
            for (int j = 0; j < 4; j++) {
                uint32_t wf[2];
                uint32_t ro = (uint32_t)((warp_n * 32 + j * 8) * ROWB) + ks + b_lane_off;
                ldsm_x2(wf, bufb + 2 * TILE_B + ro);
#pragma unroll
                for (int i = 0; i < 4; i++) {
                    mma_f16(acc[i][j], ah[i], wf);
                    mma_f16(acc[i][j], al[i], wf);
                }
            }
        }
        if (c + 1 < KCHUNKS) __pipeline_wait_prior(0);
        __syncthreads();
    }

    const int r0 = lane >> 2;
    const int q0 = (lane & 3) * 2;
#pragma unroll
    for (int j = 0; j < 4; j++) {
        const int n0 = bn + warp_n * 32 + j * 8 + q0;
#pragma unroll
        for (int i = 0; i < 4; i++) {
            const int m0 = bm + warp_m * 64 + i * 16 + r0;
            *(float2*)&Cout[(size_t)m0 * N + n0] =
                make_float2(acc[i][j][0] * WISCALE, acc[i][j][1] * WISCALE);
            *(float2*)&Cout[(size_t)(m0 + 8) * N + n0] =
                make_float2(acc[i][j][2] * WISCALE, acc[i][j][3] * WISCALE);
        }
    }
}

// ---------------- dt projection + softplus + decay ----------------
__global__ __launch_bounds__(256)
void dtdecay_kernel(const float* __restrict__ X, const float* __restrict__ W_dt,
                    const float* __restrict__ dt_bias, const float* __restrict__ A_log,
                    float* __restrict__ dts, float* __restrict__ decs)
{
    __shared__ float Xs[16][64];
    __shared__ float Ws[64][16];
    const int tid = threadIdx.x;
    const int m0  = blockIdx.x * 16;
    const int h   = tid & 15;
    const int mi  = tid >> 4;

    float acc = 0.f;
    for (int k0 = 0; k0 < D_IN; k0 += 64) {
        __syncthreads();
        *(float4*)&Xs[tid >> 4][(tid & 15) * 4] =
            *(const float4*)&X[(size_t)(m0 + (tid >> 4)) * D_IN + k0 + (tid & 15) * 4];
        *(float4*)&Ws[tid >> 2][(tid & 3) * 4] =
            *(const float4*)&W_dt[(size_t)(k0 + (tid >> 2)) * NHEAD + (tid & 3) * 4];
        __syncthreads();
#pragma unroll
        for (int k = 0; k < 64; k++)
            acc = fmaf(Xs[mi][k], Ws[k][h], acc);
    }
    const int m = m0 + mi;
    float v  = acc + dt_bias[h];
    float dt = (v > 20.f) ? v : log1pf(expf(v));
    float A  = expf(A_log[h]);
    dts[m * NHEAD + h]  = dt;
    decs[m * NHEAD + h] = expf(-A * dt);
}

// ---------------- selective scan (packed f32x2 state) ----------------
__global__ __launch_bounds__(128, 1)
void scan_kernel(const float* __restrict__ X, const float* __restrict__ Bm,
                 const float* __restrict__ Cm, const float* __restrict__ dts,
                 const float* __restrict__ decs,
                 __half* __restrict__ Yhi, __half* __restrict__ Ylo)
{
    const int bh = blockIdx.x;
    const int b  = bh >> 4;
    const int h  = bh & 15;
    const int tid = threadIdx.x;

    __shared__ __align__(16) float xb[4][PHEAD];
    __shared__ __align__(16) float Bb[4][NSTATE];
    __shared__ __align__(16) float Cb[4][NSTATE];
    __shared__ float sc[4][2];

    ull hs2[32];
#pragma unroll
    for (int i = 0; i < 32; i++) hs2[i] = 0ull;

    auto issue = [&](int t) {
        const int st = t & 3;
        const size_t m = (size_t)t * BSZ + b;
        __pipeline_memcpy_async(&xb[st][tid], X + m * D_IN + h * PHEAD + tid, 4);
        if (tid < 64)
            __pipeline_memcpy_async(&Bb[st][tid], Bm + m * HN + h * NSTATE + tid, 4);
        else
            __pipeline_memcpy_async(&Cb[st][tid - 64], Cm + m * HN + h * NSTATE + (tid - 64), 4);
        if (tid == 0) __pipeline_memcpy_async(&sc[st][0], dts  + m * NHEAD + h, 4);
        if (tid == 1) __pipeline_memcpy_async(&sc[st][1], decs + m * NHEAD + h, 4);
    };

    issue(0); __pipeline_commit();
    issue(1); __pipeline_commit();
    issue(2); __pipeline_commit();

    for (int t = 0; t < T_LEN; t++) {
        const int st = t & 3;
        __pipeline_wait_prior(2);
        __syncthreads();
        if (t + 3 < T_LEN) issue(t + 3);
        __pipeline_commit();

        const float dtv = sc[st][0];
        const float dec = sc[st][1];
        const float cc  = dtv * xb[st][tid];
        const ull dec2 = pk2(dec, dec);
        const ull cc2  = pk2(cc, cc);

        const longlong2* B2 = (const longlong2*)Bb[st];
        const longlong2* C2 = (const longlong2*)Cb[st];
        ull ya = 0ull, yb = 0ull;
#pragma unroll
        for (int j = 0; j < 16; j++) {
            longlong2 bv = B2[j];
            longlong2 cv = C2[j];
            hs2[2*j]   = fma2(dec2, hs2[2*j],   mul2(cc2, (ull)bv.x));
            ya         = fma2(hs2[2*j],   (ull)cv.x, ya);
            hs2[2*j+1] = fma2(dec2, hs2[2*j+1], mul2(cc2, (ull)bv.y));
            yb         = fma2(hs2[2*j+1], (ull)cv.y, yb);
        }
        float a0, a1, c0, c1;
        upk2(a0, a1, ya);
        upk2(c0, c1, yb);
        const float y = (a0 + a1) + (c0 + c1);

        const size_t m = (size_t)t * BSZ + b;
        __half hy = __float2half_rn(y);
        Yhi[m * D_IN + h * PHEAD + tid] = hy;
        Ylo[m * D_IN + h * PHEAD + tid] = __float2half_rn(y - __half2float(hy));
    }
}

// ---------------- policy head (fuses split-K sum + bias + relu) ------------
__global__ __launch_bounds__(256)
void head_kernel(const float* __restrict__ Zp, const float* __restrict__ b_yo,
                 const float* __restrict__ Wh, const float* __restrict__ bh,
                 float* __restrict__ out)
{
    __shared__ float Zs[4][NUNITS];
    __shared__ float Ws[64][NACT];
    const int tid = threadIdx.x;
    const int m0  = blockIdx.x * 4;
    const int n   = tid & 63;
    const int mi  = tid >> 6;

    {
        const int r  = tid >> 6;
        const int c4 = (tid & 63) * 4;
        float4 z0 = *(const float4*)&Zp[(size_t)(m0 + r) * NUNITS + c4];
        float4 z1 = *(const float4*)&Zp[(size_t)M_TOT * NUNITS + (size_t)(m0 + r) * NUNITS + c4];
        float4 by = *(const float4*)&b_yo[c4];
        float4 v;
        v.x = fmaxf(z0.x + z1.x + by.x, 0.f);
        v.y = fmaxf(z0.y + z1.y + by.y, 0.f);
        v.z = fmaxf(z0.z + z1.z + by.z, 0.f);
        v.w = fmaxf(z0.w + z1.w + by.w, 0.f);
        *(float4*)&Zs[r][c4] = v;
    }

    float acc = bh[n];
    for (int k0 = 0; k0 < NUNITS; k0 += 64) {
        __syncthreads();
#pragma unroll
        for (int j = 0; j < 4; j++) {
            int idx = tid + j * 256;
            int r = idx >> 4, c4 = (idx & 15) * 4;
            *(float4*)&Ws[r][c4] = *(const float4*)&Wh[(size_t)(k0 + r) * NACT + c4];
        }
        __syncthreads();
#pragma unroll
        for (int k = 0; k < 64; k++)
            acc = fmaf(Zs[mi][k0 + k], Ws[k][n], acc);
    }
    out[(size_t)(m0 + mi) * NACT + n] = acc;
}

// ---------------- launch ----------------
extern "C" void kernel_launch(void* const* d_in, const int* in_sizes, int n_in,
                              void* d_out, int out_size)
{
    const float* obs     = (const float*)d_in[0];
    const float* W_in    = (const float*)d_in[1];
    const float* b_in    = (const float*)d_in[2];
    const float* A_log   = (const float*)d_in[3];
    const float* dt_bias = (const float*)d_in[4];
    const float* W_dt    = (const float*)d_in[5];
    const float* W_B     = (const float*)d_in[6];
    const float* W_C     = (const float*)d_in[7];
    const float* W_yo    = (const float*)d_in[8];
    const float* b_yo    = (const float*)d_in[9];
    const float* W_head  = (const float*)d_in[10];
    const float* b_head  = (const float*)d_in[11];
    float* out = (float*)d_out;

    float *X, *Bmp, *Cmp, *dts, *dec, *Zp;
    __half *Xh, *Yhi, *Ylo, *WBh, *WCh, *Wyoh;
    __nv_bfloat16 *obsh, *obsl, *Winh, *Winl;
    cudaGetSymbolAddress((void**)&X,    g_X);
    cudaGetSymbolAddress((void**)&Xh,   g_Xh);
    cudaGetSymbolAddress((void**)&Bmp,  g_Bm);
    cudaGetSymbolAddress((void**)&Cmp,  g_Cm);
    cudaGetSymbolAddress((void**)&dts,  g_dt);
    cudaGetSymbolAddress((void**)&dec,  g_dec);
    cudaGetSymbolAddress((void**)&Yhi,  g_Yhi);
    cudaGetSymbolAddress((void**)&Ylo,  g_Ylo);
    cudaGetSymbolAddress((void**)&Zp,   g_Zp);
    cudaGetSymbolAddress((void**)&obsh, g_obs_hi);
    cudaGetSymbolAddress((void**)&obsl, g_obs_lo);
    cudaGetSymbolAddress((void**)&Winh, g_Win_hi);
    cudaGetSymbolAddress((void**)&Winl, g_Win_lo);
    cudaGetSymbolAddress((void**)&WBh,  g_WB_h);
    cudaGetSymbolAddress((void**)&WCh,  g_WC_h);
    cudaGetSymbolAddress((void**)&Wyoh, g_Wyo_h);

    static cudaStream_t sB = nullptr, sC = nullptr;
    static cudaEvent_t eFork, eWB, eWC, eWyo, eX, eC, eD;
    if (!sB) {
        cudaStreamCreateWithFlags(&sB, cudaStreamNonBlocking);
        cudaStreamCreateWithFlags(&sC, cudaStreamNonBlocking);
        cudaEventCreateWithFlags(&eFork, cudaEventDisableTiming);
        cudaEventCreateWithFlags(&eWB,  cudaEventDisableTiming);
        cudaEventCreateWithFlags(&eWC,  cudaEventDisableTiming);
        cudaEventCreateWithFlags(&eWyo, cudaEventDisableTiming);
        cudaEventCreateWithFlags(&eX,   cudaEventDisableTiming);
        cudaEventCreateWithFlags(&eC,   cudaEventDisableTiming);
        cudaEventCreateWithFlags(&eD,   cudaEventDisableTiming);

        cudaFuncSetAttribute(mma_gemm_bf3<8>, cudaFuncAttributeMaxDynamicSharedMemorySize, SMEM_BF16);
        cudaFuncSetAttribute(mma_gemm_h1<64>, cudaFuncAttributeMaxDynamicSharedMemorySize, SMEM_F16_2);
        cudaFuncSetAttribute(mma_gemm_h2<32>, cudaFuncAttributeMaxDynamicSharedMemorySize, SMEM_F16_3);
    }

    cudaEventRecord(eFork, 0);
    cudaStreamWaitEvent(sB, eFork, 0);
    cudaStreamWaitEvent(sC, eFork, 0);

    // side streams: weight conversions
    transconv_h_kernel<<<dim3(HN / 32, D_IN / 32), dim3(32, 8), 0, sB>>>(W_B, WBh, D_IN, HN);
    cudaEventRecord(eWB, sB);
    transconv_h_kernel<<<dim3(HN / 32, D_IN / 32), dim3(32, 8), 0, sC>>>(W_C, WCh, D_IN, HN);
    cudaEventRecord(eWC, sC);
    transconv_h_kernel<<<dim3(NUNITS / 32, D_IN / 32), dim3(32, 8), 0, sC>>>(W_yo, Wyoh, D_IN, NUNITS);
    cudaEventRecord(eWyo, sC);

    // main: obs conv, Win conv, GEMM1 (bf16x3) -> X fp32 + Xh fp16
    rowconv_kernel<<<(M_TOT * OBS_DIM / 4 + 255) / 256, 256>>>(obs, obsh, obsl, M_TOT * OBS_DIM);
    transconv_kernel<<<dim3(D_IN / 32, OBS_DIM / 32), dim3(32, 8)>>>(W_in, Winh, Winl, OBS_DIM, D_IN);
    mma_gemm_bf3<8><<<dim3(D_IN / 128, M_TOT / 128), 256, SMEM_BF16>>>(
        obsh, obsl, Winh, Winl, b_in, X, Xh, M_TOT, D_IN, OBS_DIM);
    cudaEventRecord(eX, 0);

    // B projection (fp16 1-pass) on main
    cudaStreamWaitEvent(0, eWB, 0);
    mma_gemm_h1<64><<<dim3(HN / 128, M_TOT / 128), 256, SMEM_F16_2>>>(
        Xh, WBh, Bmp, M_TOT, HN, D_IN);

    // C projection on stream B
    cudaStreamWaitEvent(sB, eX, 0);
    cudaStreamWaitEvent(sB, eWC, 0);
    mma_gemm_h1<64><<<dim3(HN / 128, M_TOT / 128), 256, SMEM_F16_2, sB>>>(
        Xh, WCh, Cmp, M_TOT, HN, D_IN);
    cudaEventRecord(eC, sB);

    // dt/decay on stream C
    cudaStreamWaitEvent(sC, eX, 0);
    dtdecay_kernel<<<M_TOT / 16, 256, 0, sC>>>(X, W_dt, dt_bias, A_log, dts, dec);
    cudaEventRecord(eD, sC);

    // join -> scan (writes Y fp16 hi/lo)
    cudaStreamWaitEvent(0, eC, 0);
    cudaStreamWaitEvent(0, eD, 0);
    scan_kernel<<<BSZ * NHEAD, 128>>>(X, Bmp, Cmp, dts, dec, Yhi, Ylo);

    // yo projection (fp16 2-pass, split-K=2) + head
    cudaStreamWaitEvent(0, eWyo, 0);
    mma_gemm_h2<32><<<dim3(NUNITS / 128, M_TOT / 128, 2), 256, SMEM_F16_3>>>(
        Yhi, Ylo, Wyoh, Zp, M_TOT, NUNITS, D_IN);
    head_kernel<<<M_TOT / 4, 256>>>(Zp, b_yo, W_head, b_head, out);
}

// round 8
// speedup vs baseline: 6.9604x; 1.0561x over previous
#include <cuda_runtime.h>
#include <cuda_pipeline.h>
#include <cuda_bf16.h>
#include <cuda_fp16.h>
#include <math.h>
#include <stdint.h>

// ---------------- problem dims ----------------
#define T_LEN   512
#define BSZ     8
#define M_TOT   (T_LEN * BSZ)      // 4096
#define M_HALF  (M_TOT / 2)        // 2048
#define OBS_DIM 256
#define D_IN    2048
#define NHEAD   16
#define NSTATE  64
#define PHEAD   128
#define NUNITS  256
#define NACT    64
#define HN      (NHEAD * NSTATE)    // 1024
#define WSCALE  32.0f
#define WISCALE (1.0f / 32.0f)

// ---------------- scratch ----------------
__device__ float          g_X   [M_TOT * D_IN];
__device__ __half         g_Xh  [M_TOT * D_IN];
__device__ float          g_Bm  [M_TOT * HN];
__device__ float          g_Cm  [M_TOT * HN];
__device__ float          g_dt  [M_TOT * NHEAD];
__device__ float          g_dec [M_TOT * NHEAD];
__device__ __half         g_Yhi [M_TOT * D_IN];
__device__ __half         g_Ylo [M_TOT * D_IN];
__device__ float          g_Zp  [2 * M_TOT * NUNITS];
__device__ unsigned long long g_hstate[128 * 128 * 32];   // scan state carry (4MB)
__device__ __nv_bfloat16  g_obs_hi[M_TOT * OBS_DIM];
__device__ __nv_bfloat16  g_obs_lo[M_TOT * OBS_DIM];
__device__ __nv_bfloat16  g_Win_hi[D_IN * OBS_DIM];
__device__ __nv_bfloat16  g_Win_lo[D_IN * OBS_DIM];
__device__ __half         g_WB_h [HN * D_IN];
__device__ __half         g_WC_h [HN * D_IN];
__device__ __half         g_Wyo_h[NUNITS * D_IN];

// ---------------- helpers ----------------
__device__ __forceinline__ uint32_t smem_u32(const void* p) {
    uint32_t a;
    asm("{ .reg .u64 t; cvta.to.shared.u64 t, %1; cvt.u32.u64 %0, t; }" : "=r"(a) : "l"(p));
    return a;
}
__device__ __forceinline__ void ldsm_x4(uint32_t* r, uint32_t addr) {
    asm volatile("ldmatrix.sync.aligned.m8n8.x4.shared.b16 {%0,%1,%2,%3}, [%4];"
                 : "=r"(r[0]), "=r"(r[1]), "=r"(r[2]), "=r"(r[3]) : "r"(addr));
}
__device__ __forceinline__ void ldsm_x2(uint32_t* r, uint32_t addr) {
    asm volatile("ldmatrix.sync.aligned.m8n8.x2.shared.b16 {%0,%1}, [%2];"
                 : "=r"(r[0]), "=r"(r[1]) : "r"(addr));
}
__device__ __forceinline__ void mma_bf16(float* c, const uint32_t* a, const uint32_t* b) {
    asm volatile("mma.sync.aligned.m16n8k16.row.col.f32.bf16.bf16.f32 "
                 "{%0,%1,%2,%3}, {%4,%5,%6,%7}, {%8,%9}, {%0,%1,%2,%3};"
                 : "+f"(c[0]), "+f"(c[1]), "+f"(c[2]), "+f"(c[3])
                 : "r"(a[0]), "r"(a[1]), "r"(a[2]), "r"(a[3]), "r"(b[0]), "r"(b[1]));
}
__device__ __forceinline__ void mma_f16(float* c, const uint32_t* a, const uint32_t* b) {
    asm volatile("mma.sync.aligned.m16n8k16.row.col.f32.f16.f16.f32 "
                 "{%0,%1,%2,%3}, {%4,%5,%6,%7}, {%8,%9}, {%0,%1,%2,%3};"
                 : "+f"(c[0]), "+f"(c[1]), "+f"(c[2]), "+f"(c[3])
                 : "r"(a[0]), "r"(a[1]), "r"(a[2]), "r"(a[3]), "r"(b[0]), "r"(b[1]));
}
typedef unsigned long long ull;
__device__ __forceinline__ ull pk2(float lo, float hi) {
    ull r; asm("mov.b64 %0, {%1, %2};" : "=l"(r) : "f"(lo), "f"(hi)); return r;
}
__device__ __forceinline__ void upk2(float& lo, float& hi, ull v) {
    asm("mov.b64 {%0, %1}, %2;" : "=f"(lo), "=f"(hi) : "l"(v));
}
__device__ __forceinline__ ull fma2(ull a, ull b, ull c) {
    ull d; asm("fma.rn.f32x2 %0, %1, %2, %3;" : "=l"(d) : "l"(a), "l"(b), "l"(c)); return d;
}
__device__ __forceinline__ ull mul2(ull a, ull b) {
    ull d; asm("mul.rn.f32x2 %0, %1, %2;" : "=l"(d) : "l"(a), "l"(b)); return d;
}

// ---------------- conversion kernels ----------------
__global__ void rowconv_kernel(const float* __restrict__ src,
                               __nv_bfloat16* __restrict__ hi,
                               __nv_bfloat16* __restrict__ lo, int n)
{
    int i = blockIdx.x * blockDim.x + threadIdx.x;
    if (i * 4 >= n) return;
    float4 v = *(const float4*)(src + i * 4);
    float vv[4] = {v.x, v.y, v.z, v.w};
#pragma unroll
    for (int j = 0; j < 4; j++) {
        __nv_bfloat16 h = __float2bfloat16(vv[j]);
        hi[i * 4 + j] = h;
        lo[i * 4 + j] = __float2bfloat16(vv[j] - __bfloat162float(h));
    }
}

__global__ void transconv_kernel(const float* __restrict__ W,
                                 __nv_bfloat16* __restrict__ Thi,
                                 __nv_bfloat16* __restrict__ Tlo, int K, int N)
{
    __shared__ float s[32][33];
    int tx = threadIdx.x, ty = threadIdx.y;
    int n0 = blockIdx.x * 32, k0 = blockIdx.y * 32;
#pragma unroll
    for (int i = 0; i < 4; i++)
        s[ty + i * 8][tx] = W[(size_t)(k0 + ty + i * 8) * N + n0 + tx];
    __syncthreads();
#pragma unroll
    for (int i = 0; i < 4; i++) {
        int n = n0 + ty + i * 8, k = k0 + tx;
        float v = s[tx][ty + i * 8];
        __nv_bfloat16 h = __float2bfloat16(v);
        Thi[(size_t)n * K + k] = h;
        Tlo[(size_t)n * K + k] = __float2bfloat16(v - __bfloat162float(h));
    }
}

__global__ void transconv_h_kernel(const float* __restrict__ W,
                                   __half* __restrict__ Th, int K, int N)
{
    __shared__ float s[32][33];
    int tx = threadIdx.x, ty = threadIdx.y;
    int n0 = blockIdx.x * 32, k0 = blockIdx.y * 32;
#pragma unroll
    for (int i = 0; i < 4; i++)
        s[ty + i * 8][tx] = W[(size_t)(k0 + ty + i * 8) * N + n0 + tx];
    __syncthreads();
#pragma unroll
    for (int i = 0; i < 4; i++) {
        int n = n0 + ty + i * 8, k = k0 + tx;
        Th[(size_t)n * K + k] = __float2half_rn(s[tx][ty + i * 8] * WSCALE);
    }
}

// ---------------- tile geometry ----------------
#define ROWB      80
#define TILE_B    (128 * ROWB)
#define BUF_B4    (4 * TILE_B)
#define SMEM_BF16 (2 * BUF_B4)
#define BUF_B3    (3 * TILE_B)
#define SMEM_F16_3 (2 * BUF_B3)
#define BUF_B2    (2 * TILE_B)
#define SMEM_F16_2 (2 * BUF_B2)

// ---------------- bf16x3 GEMM (GEMM1) ----------------
template<int KCHUNKS>
__global__ __launch_bounds__(256, 2)
void mma_gemm_bf3(const __nv_bfloat16* __restrict__ Ahi, const __nv_bfloat16* __restrict__ Alo,
                  const __nv_bfloat16* __restrict__ Bhi, const __nv_bfloat16* __restrict__ Blo,
                  const float* __restrict__ bias,
                  float* __restrict__ Cout, __half* __restrict__ Ch,
                  int M, int N, int K)
{
    extern __shared__ char smem[];
    const uint32_t sbase = smem_u32(smem);
    const int tid  = threadIdx.x;
    const int lane = tid & 31, wid = tid >> 5;
    const int warp_m = wid >> 2;
    const int warp_n = wid & 3;
    const int bn = blockIdx.x * 128;
    const int bm = blockIdx.y * 128;

    const __nv_bfloat16* srcs[4] = {Ahi, Alo, Bhi, Blo};

    auto load_chunk = [&](int c, int buf) {
#pragma unroll
        for (int w = 0; w < 4; w++) {
            const int rowbase = (w < 2) ? bm : bn;
            const __nv_bfloat16* src = srcs[w];
#pragma unroll
            for (int t = 0; t < 2; t++) {
                int idx = tid + t * 256;
                int row = idx >> 2, seg = idx & 3;
                char* dst = smem + buf * BUF_B4 + w * TILE_B + row * ROWB + seg * 16;
                const char* s = (const char*)src +
                    ((size_t)(rowbase + row) * K + (size_t)c * 32) * 2 + seg * 16;
                __pipeline_memcpy_async(dst, s, 16);
            }
        }
    };

    float acc[4][4][4];
#pragma unroll
    for (int i = 0; i < 4; i++)
#pragma unroll
        for (int j = 0; j < 4; j++)
#pragma unroll
            for (int q = 0; q < 4; q++) acc[i][j][q] = 0.f;

    load_chunk(0, 0);
    __pipeline_commit();
    __pipeline_wait_prior(0);
    __syncthreads();

    const uint32_t a_lane_off = (uint32_t)((lane & 15) * ROWB + (lane >> 4) * 16);
    const uint32_t b_lane_off = (uint32_t)((lane & 7) * ROWB + ((lane >> 3) & 1) * 16);

    for (int c = 0; c < KCHUNKS; c++) {
        if (c + 1 < KCHUNKS) { load_chunk(c + 1, (c + 1) & 1); __pipeline_commit(); }
        const uint32_t bufb = sbase + (c & 1) * BUF_B4;
#pragma unroll
        for (int s = 0; s < 2; s++) {
            uint32_t ah[4][4], al[4][4];
            const uint32_t ks = s * 32;
#pragma unroll
            for (int i = 0; i < 4; i++) {
                uint32_t ro = (uint32_t)((warp_m * 64 + i * 16) * ROWB) + ks + a_lane_off;
                ldsm_x4(ah[i], bufb + 0 * TILE_B + ro);
                ldsm_x4(al[i], bufb + 1 * TILE_B + ro);
            }
#pragma unroll
            for (int j = 0; j < 4; j++) {
                uint32_t bh[2], bl[2];
                uint32_t ro = (uint32_t)((warp_n * 32 + j * 8) * ROWB) + ks + b_lane_off;
                ldsm_x2(bh, bufb + 2 * TILE_B + ro);
                ldsm_x2(bl, bufb + 3 * TILE_B + ro);
#pragma unroll
                for (int i = 0; i < 4; i++) {
                    mma_bf16(acc[i][j], ah[i], bh);
                    mma_bf16(acc[i][j], ah[i], bl);
                    mma_bf16(acc[i][j], al[i], bh);
                }
            }
        }
        if (c + 1 < KCHUNKS) __pipeline_wait_prior(0);
        __syncthreads();
    }

    const int r0 = lane >> 2;
    const int q0 = (lane & 3) * 2;
#pragma unroll
    for (int j = 0; j < 4; j++) {
        const int n0 = bn + warp_n * 32 + j * 8 + q0;
        float b0 = bias[n0], b1 = bias[n0 + 1];
#pragma unroll
        for (int i = 0; i < 4; i++) {
            const int m0 = bm + warp_m * 64 + i * 16 + r0;
            float v0 = fmaxf(acc[i][j][0] + b0, 0.f);
            float v1 = fmaxf(acc[i][j][1] + b1, 0.f);
            float v2 = fmaxf(acc[i][j][2] + b0, 0.f);
            float v3 = fmaxf(acc[i][j][3] + b1, 0.f);
            *(float2*)&Cout[(size_t)m0 * N + n0]       = make_float2(v0, v1);
            *(float2*)&Cout[(size_t)(m0 + 8) * N + n0] = make_float2(v2, v3);
            __half2 hp0 = {__float2half_rn(v0), __float2half_rn(v1)};
            __half2 hp1 = {__float2half_rn(v2), __float2half_rn(v3)};
            *(__half2*)&Ch[(size_t)m0 * N + n0]       = hp0;
            *(__half2*)&Ch[(size_t)(m0 + 8) * N + n0] = hp1;
        }
    }
}

// ---------------- fp16 single-pass GEMM (B/C projections) ----------------
template<int KCHUNKS>
__global__ __launch_bounds__(256, 2)
void mma_gemm_h1(const __half* __restrict__ A, const __half* __restrict__ Wm,
                 float* __restrict__ Cout, int M, int N, int K)
{
    extern __shared__ char smem[];
    const uint32_t sbase = smem_u32(smem);
    const int tid  = threadIdx.x;
    const int lane = tid & 31, wid = tid >> 5;
    const int warp_m = wid >> 2;
    const int warp_n = wid & 3;
    const int bn = blockIdx.x * 128;
    const int bm = blockIdx.y * 128;

    const __half* srcs[2] = {A, Wm};

    auto load_chunk = [&](int c, int buf) {
#pragma unroll
        for (int w = 0; w < 2; w++) {
            const int rowbase = (w == 0) ? bm : bn;
            const __half* src = srcs[w];
#pragma unroll
            for (int t = 0; t < 2; t++) {
                int idx = tid + t * 256;
                int row = idx >> 2, seg = idx & 3;
                char* dst = smem + buf * BUF_B2 + w * TILE_B + row * ROWB + seg * 16;
                const char* s = (const char*)src +
                    ((size_t)(rowbase + row) * K + (size_t)c * 32) * 2 + seg * 16;
                __pipeline_memcpy_async(dst, s, 16);
            }
        }
    };

    float acc[4][4][4];
#pragma unroll
    for (int i = 0; i < 4; i++)
#pragma unroll
        for (int j = 0; j < 4; j++)
#pragma unroll
            for (int q = 0; q < 4; q++) acc[i][j][q] = 0.f;

    load_chunk(0, 0);
    __pipeline_commit();
    __pipeline_wait_prior(0);
    __syncthreads();

    const uint32_t a_lane_off = (uint32_t)((lane & 15) * ROWB + (lane >> 4) * 16);
    const uint32_t b_lane_off = (uint32_t)((lane & 7) * ROWB + ((lane >> 3) & 1) * 16);

    for (int c = 0; c < KCHUNKS; c++) {
        if (c + 1 < KCHUNKS) { load_chunk(c + 1, (c + 1) & 1); __pipeline_commit(); }
        const uint32_t bufb = sbase + (c & 1) * BUF_B2;
#pragma unroll
        for (int s = 0; s < 2; s++) {
            uint32_t af[4][4];
            const uint32_t ks = s * 32;
#pragma unroll
            for (int i = 0; i < 4; i++) {
                uint32_t ro = (uint32_t)((warp_m * 64 + i * 16) * ROWB) + ks + a_lane_off;
                ldsm_x4(af[i], bufb + 0 * TILE_B + ro);
            }
#pragma unroll
            for (int j = 0; j < 4; j++) {
                uint32_t wf[2];
                uint32_t ro = (uint32_t)((warp_n * 32 + j * 8) * ROWB) + ks + b_lane_off;
                ldsm_x2(wf, bufb + 1 * TILE_B + ro);
#pragma unroll
                for (int i = 0; i < 4; i++)
                    mma_f16(acc[i][j], af[i], wf);
            }
        }
        if (c + 1 < KCHUNKS) __pipeline_wait_prior(0);
        __syncthreads();
    }

    const int r0 = lane >> 2;
    const int q0 = (lane & 3) * 2;
#pragma unroll
    for (int j = 0; j < 4; j++) {
        const int n0 = bn + warp_n * 32 + j * 8 + q0;
#pragma unroll
        for (int i = 0; i < 4; i++) {
            const int m0 = bm + warp_m * 64 + i * 16 + r0;
            *(float2*)&Cout[(size_t)m0 * N + n0] =
                make_float2(acc[i][j][0] * WISCALE, acc[i][j][1] * WISCALE);
            *(float2*)&Cout[(size_t)(m0 + 8) * N + n0] =
                make_float2(acc[i][j][2] * WISCALE, acc[i][j][3] * WISCALE);
        }
    }
}

// ---------------- fp16 2-pass GEMM (yo projection, split-K) ----------------
template<int KCHUNKS>
__global__ __launch_bounds__(256, 2)
void mma_gemm_h2(const __half* __restrict__ Ahi, const __half* __restrict__ Alo,
                 const __half* __restrict__ Wm,
                 float* __restrict__ Cout, int M, int N, int K, size_t zstride)
{
    extern __shared__ char smem[];
    const uint32_t sbase = smem_u32(smem);
    const int tid  = threadIdx.x;
    const int lane = tid & 31, wid = tid >> 5;
    const int warp_m = wid >> 2;
    const int warp_n = wid & 3;
    const int bn = blockIdx.x * 128;
    const int bm = blockIdx.y * 128;
    const int zoff = blockIdx.z * KCHUNKS;
    Cout += (size_t)blockIdx.z * zstride;

    const __half* srcs[3] = {Ahi, Alo, Wm};

    auto load_chunk = [&](int gc, int buf) {
#pragma unroll
        for (int w = 0; w < 3; w++) {
            const int rowbase = (w < 2) ? bm : bn;
            const __half* src = srcs[w];
#pragma unroll
            for (int t = 0; t < 2; t++) {
                int idx = tid + t * 256;
                int row = idx >> 2, seg = idx & 3;
                char* dst = smem + buf * BUF_B3 + w * TILE_B + row * ROWB + seg * 16;
                const char* s = (const char*)src +
                    ((size_t)(rowbase + row) * K + (size_t)gc * 32) * 2 + seg * 16;
                __pipeline_memcpy_async(dst, s, 16);
            }
        }
    };

    float acc[4][4][4];
#pragma unroll
    for (int i = 0; i < 4; i++)
#pragma unroll
        for (int j = 0; j < 4; j++)
#pragma unroll
            for (int q = 0; q < 4; q++) acc[i][j][q] = 0.f;

    load_chunk(zoff, 0);
    __pipeline_commit();
    __pipeline_wait_prior(0);
    __syncthreads();

    const uint32_t a_lane_off = (uint32_t)((lane & 15) * ROWB + (lane >> 4) * 16);
    const uint32_t b_lane_off = (uint32_t)((lane & 7) * ROWB + ((lane >> 3) & 1) * 16);

    for (int c = 0; c < KCHUNKS; c++) {
        if (c + 1 < KCHUNKS) { load_chunk(zoff + c + 1, (c + 1) & 1); __pipeline_commit(); }
        const uint32_t bufb = sbase + (c & 1) * BUF_B3;
#pragma unroll
        for (int s = 0; s < 2; s++) {
            uint32_t ah[4][4], al[4][4];
            const uint32_t ks = s * 32;
#pragma unroll
            for (int i = 0; i < 4; i++) {
                uint32_t ro = (uint32_t)((warp_m * 64 + i * 16) * ROWB) + ks + a_lane_off;
                ldsm_x4(ah[i], bufb + 0 * TILE_B + ro);
                ldsm_x4(al[i], bufb + 1 * TILE_B + ro);
            }
#pragma unroll
            for (int j = 0; j < 4; j++) {
                uint32_t wf[2];
                uint32_t ro = (uint32_t)((warp_n * 32 + j * 8) * ROWB) + ks + b_lane_off;
                ldsm_x2(wf, bufb + 2 * TILE_B + ro);
#pragma unroll
                for (int i = 0; i < 4; i++) {
                    mma_f16(acc[i][j], ah[i], wf);
                    mma_f16(acc[i][j], al[i], wf);
                }
            }
        }
        if (c + 1 < KCHUNKS) __pipeline_wait_prior(0);
        __syncthreads();
    }

    const int r0 = lane >> 2;
    const int q0 = (lane & 3) * 2;
#pragma unroll
    for (int j = 0; j < 4; j++) {
        const int n0 = bn + warp_n * 32 + j * 8 + q0;
#pragma unroll
        for (int i = 0; i < 4; i++) {
            const int m0 = bm + warp_m * 64 + i * 16 + r0;
            *(float2*)&Cout[(size_t)m0 * N + n0] =
                make_float2(acc[i][j][0] * WISCALE, acc[i][j][1] * WISCALE);
            *(float2*)&Cout[(size_t)(m0 + 8) * N + n0] =
                make_float2(acc[i][j][2] * WISCALE, acc[i][j][3] * WISCALE);
        }
    }
}

// ---------------- dt projection + softplus + decay ----------------
__global__ __launch_bounds__(256)
void dtdecay_kernel(const float* __restrict__ X, const float* __restrict__ W_dt,
                    const float* __restrict__ dt_bias, const float* __restrict__ A_log,
                    float* __restrict__ dts, float* __restrict__ decs)
{
    __shared__ float Xs[16][64];
    __shared__ float Ws[64][16];
    const int tid = threadIdx.x;
    const int m0  = blockIdx.x * 16;
    const int h   = tid & 15;
    const int mi  = tid >> 4;

    float acc = 0.f;
    for (int k0 = 0; k0 < D_IN; k0 += 64) {
        __syncthreads();
        *(float4*)&Xs[tid >> 4][(tid & 15) * 4] =
            *(const float4*)&X[(size_t)(m0 + (tid >> 4)) * D_IN + k0 + (tid & 15) * 4];
        *(float4*)&Ws[tid >> 2][(tid & 3) * 4] =
            *(const float4*)&W_dt[(size_t)(k0 + (tid >> 2)) * NHEAD + (tid & 3) * 4];
        __syncthreads();
#pragma unroll
        for (int k = 0; k < 64; k++)
            acc = fmaf(Xs[mi][k], Ws[k][h], acc);
    }
    const int m = m0 + mi;
    float v  = acc + dt_bias[h];
    float dt = (v > 20.f) ? v : log1pf(expf(v));
    float A  = expf(A_log[h]);
    dts[m * NHEAD + h]  = dt;
    decs[m * NHEAD + h] = expf(-A * dt);
}

// ---------------- selective scan (chunked, 2 steps per barrier) ----------
__global__ __launch_bounds__(128, 1)
void scan_kernel(const float* __restrict__ X, const float* __restrict__ Bm,
                 const float* __restrict__ Cm, const float* __restrict__ dts,
                 const float* __restrict__ decs,
                 __half* __restrict__ Yhi, __half* __restrict__ Ylo,
                 ull* __restrict__ hstate, int t0, int t1, int first)
{
    const int bh = blockIdx.x;
    const int b  = bh >> 4;
    const int h  = bh & 15;
    const int tid = threadIdx.x;

    __shared__ __align__(16) float xb[4][2][PHEAD];
    __shared__ __align__(16) float Bb[4][2][NSTATE];
    __shared__ __align__(16) float Cb[4][2][NSTATE];
    __shared__ float sc[4][2][2];

    ull* hptr = hstate + ((size_t)bh * 128 + tid) * 32;
    ull hs2[32];
    if (first) {
#pragma unroll
        for (int i = 0; i < 32; i++) hs2[i] = 0ull;
    } else {
#pragma unroll
        for (int i = 0; i < 32; i++) hs2[i] = hptr[i];
    }

    const int NP = (t1 - t0) >> 1;   // pairs of timesteps

    auto issue = [&](int p) {
        const int st = p & 3;
#pragma unroll
        for (int u = 0; u < 2; u++) {
            const int t = t0 + 2 * p + u;
            const size_t m = (size_t)t * BSZ + b;
            __pipeline_memcpy_async(&xb[st][u][tid], X + m * D_IN + h * PHEAD + tid, 4);
            if (tid < 64)
                __pipeline_memcpy_async(&Bb[st][u][tid], Bm + m * HN + h * NSTATE + tid, 4);
            else
                __pipeline_memcpy_async(&Cb[st][u][tid - 64], Cm + m * HN + h * NSTATE + (tid - 64), 4);
            if (tid == 0) __pipeline_memcpy_async(&sc[st][u][0], dts  + m * NHEAD + h, 4);
            if (tid == 1) __pipeline_memcpy_async(&sc[st][u][1], decs + m * NHEAD + h, 4);
        }
    };

    issue(0); __pipeline_commit();
    issue(1); __pipeline_commit();
    issue(2); __pipeline_commit();

    for (int p = 0; p < NP; p++) {
        const int st = p & 3;
        __pipeline_wait_prior(2);
        __syncthreads();
        if (p + 3 < NP) issue(p + 3);
        __pipeline_commit();

#pragma unroll
        for (int u = 0; u < 2; u++) {
            const float dtv = sc[st][u][0];
            const float dec = sc[st][u][1];
            const float cc  = dtv * xb[st][u][tid];
            const ull dec2 = pk2(dec, dec);
            const ull cc2  = pk2(cc, cc);

            const longlong2* B2 = (const longlong2*)Bb[st][u];
            const longlong2* C2 = (const longlong2*)Cb[st][u];
            ull ya = 0ull, yb = 0ull;
#pragma unroll
            for (int j = 0; j < 16; j++) {
                longlong2 bv = B2[j];
                longlong2 cv = C2[j];
                hs2[2*j]   = fma2(dec2, hs2[2*j],   mul2(cc2, (ull)bv.x));
                ya         = fma2(hs2[2*j],   (ull)cv.x, ya);
                hs2[2*j+1] = fma2(dec2, hs2[2*j+1], mul2(cc2, (ull)bv.y));
                yb         = fma2(hs2[2*j+1], (ull)cv.y, yb);
            }
            float a0, a1, c0, c1;
            upk2(a0, a1, ya);
            upk2(c0, c1, yb);
            const float y = (a0 + a1) + (c0 + c1);

            const int t = t0 + 2 * p + u;
            const size_t m = (size_t)t * BSZ + b;
            __half hy = __float2half_rn(y);
            Yhi[m * D_IN + h * PHEAD + tid] = hy;
            Ylo[m * D_IN + h * PHEAD + tid] = __float2half_rn(y - __half2float(hy));
        }
    }

    if (t1 < T_LEN) {
#pragma unroll
        for (int i = 0; i < 32; i++) hptr[i] = hs2[i];
    }
}

// ---------------- policy head (fuses split-K sum + bias + relu) ------------
__global__ __launch_bounds__(256)
void head_kernel(const float* __restrict__ Zp, const float* __restrict__ b_yo,
                 const float* __restrict__ Wh, const float* __restrict__ bh,
                 float* __restrict__ out)
{
    __shared__ float Zs[4][NUNITS];
    __shared__ float Ws[64][NACT];
    const int tid = threadIdx.x;
    const int m0  = blockIdx.x * 4;
    const int n   = tid & 63;
    const int mi  = tid >> 6;

    {
        const int r  = tid >> 6;
        const int c4 = (tid & 63) * 4;
        float4 z0 = *(const float4*)&Zp[(size_t)(m0 + r) * NUNITS + c4];
        float4 z1 = *(const float4*)&Zp[(size_t)M_TOT * NUNITS + (size_t)(m0 + r) * NUNITS + c4];
        float4 by = *(const float4*)&b_yo[c4];
        float4 v;
        v.x = fmaxf(z0.x + z1.x + by.x, 0.f);
        v.y = fmaxf(z0.y + z1.y + by.y, 0.f);
        v.z = fmaxf(z0.z + z1.z + by.z, 0.f);
        v.w = fmaxf(z0.w + z1.w + by.w, 0.f);
        *(float4*)&Zs[r][c4] = v;
    }

    float acc = bh[n];
    for (int k0 = 0; k0 < NUNITS; k0 += 64) {
        __syncthreads();
#pragma unroll
        for (int j = 0; j < 4; j++) {
            int idx = tid + j * 256;
            int r = idx >> 4, c4 = (idx & 15) * 4;
            *(float4*)&Ws[r][c4] = *(const float4*)&Wh[(size_t)(k0 + r) * NACT + c4];
        }
        __syncthreads();
#pragma unroll
        for (int k = 0; k < 64; k++)
            acc = fmaf(Zs[mi][k0 + k], Ws[k][n], acc);
    }
    out[(size_t)(m0 + mi) * NACT + n] = acc;
}

// ---------------- launch (T-split pipeline, graph-capturable) ---------------
extern "C" void kernel_launch(void* const* d_in, const int* in_sizes, int n_in,
                              void* d_out, int out_size)
{
    const float* obs     = (const float*)d_in[0];
    const float* W_in    = (const float*)d_in[1];
    const float* b_in    = (const float*)d_in[2];
    const float* A_log   = (const float*)d_in[3];
    const float* dt_bias = (const float*)d_in[4];
    const float* W_dt    = (const float*)d_in[5];
    const float* W_B     = (const float*)d_in[6];
    const float* W_C     = (const float*)d_in[7];
    const float* W_yo    = (const float*)d_in[8];
    const float* b_yo    = (const float*)d_in[9];
    const float* W_head  = (const float*)d_in[10];
    const float* b_head  = (const float*)d_in[11];
    float* out = (float*)d_out;

    float *X, *Bmp, *Cmp, *dts, *dec, *Zp;
    __half *Xh, *Yhi, *Ylo, *WBh, *WCh, *Wyoh;
    __nv_bfloat16 *obsh, *obsl, *Winh, *Winl;
    ull* hst;
    cudaGetSymbolAddress((void**)&X,    g_X);
    cudaGetSymbolAddress((void**)&Xh,   g_Xh);
    cudaGetSymbolAddress((void**)&Bmp,  g_Bm);
    cudaGetSymbolAddress((void**)&Cmp,  g_Cm);
    cudaGetSymbolAddress((void**)&dts,  g_dt);
    cudaGetSymbolAddress((void**)&dec,  g_dec);
    cudaGetSymbolAddress((void**)&Yhi,  g_Yhi);
    cudaGetSymbolAddress((void**)&Ylo,  g_Ylo);
    cudaGetSymbolAddress((void**)&Zp,   g_Zp);
    cudaGetSymbolAddress((void**)&hst,  g_hstate);
    cudaGetSymbolAddress((void**)&obsh, g_obs_hi);
    cudaGetSymbolAddress((void**)&obsl, g_obs_lo);
    cudaGetSymbolAddress((void**)&Winh, g_Win_hi);
    cudaGetSymbolAddress((void**)&Winl, g_Win_lo);
    cudaGetSymbolAddress((void**)&WBh,  g_WB_h);
    cudaGetSymbolAddress((void**)&WCh,  g_WC_h);
    cudaGetSymbolAddress((void**)&Wyoh, g_Wyo_h);

    static cudaStream_t sB = nullptr, sC = nullptr;
    static cudaEvent_t eFork, eWB, eWC, eWyo, eWin, eX, eB1, eB2, eC1, eC2, eS1, eS2;
    if (!sB) {
        cudaStreamCreateWithFlags(&sB, cudaStreamNonBlocking);
        cudaStreamCreateWithFlags(&sC, cudaStreamNonBlocking);
        cudaEvent_t* evs[12] = {&eFork, &eWB, &eWC, &eWyo, &eWin, &eX,
                                &eB1, &eB2, &eC1, &eC2, &eS1, &eS2};
        for (int i = 0; i < 12; i++)
            cudaEventCreateWithFlags(evs[i], cudaEventDisableTiming);

        cudaFuncSetAttribute(mma_gemm_bf3<8>, cudaFuncAttributeMaxDynamicSharedMemorySize, SMEM_BF16);
        cudaFuncSetAttribute(mma_gemm_h1<64>, cudaFuncAttributeMaxDynamicSharedMemorySize, SMEM_F16_2);
        cudaFuncSetAttribute(mma_gemm_h2<32>, cudaFuncAttributeMaxDynamicSharedMemorySize, SMEM_F16_3);
    }

    cudaEventRecord(eFork, 0);
    cudaStreamWaitEvent(sB, eFork, 0);
    cudaStreamWaitEvent(sC, eFork, 0);

    // side-stream weight conversions
    transconv_h_kernel<<<dim3(HN / 32, D_IN / 32), dim3(32, 8), 0, sB>>>(W_B, WBh, D_IN, HN);
    cudaEventRecord(eWB, sB);
    transconv_kernel<<<dim3(D_IN / 32, OBS_DIM / 32), dim3(32, 8), 0, sC>>>(W_in, Winh, Winl, OBS_DIM, D_IN);
    cudaEventRecord(eWin, sC);
    transconv_h_kernel<<<dim3(HN / 32, D_IN / 32), dim3(32, 8), 0, sC>>>(W_C, WCh, D_IN, HN);
    cudaEventRecord(eWC, sC);
    transconv_h_kernel<<<dim3(NUNITS / 32, D_IN / 32), dim3(32, 8), 0, sC>>>(W_yo, Wyoh, D_IN, NUNITS);
    cudaEventRecord(eWyo, sC);

    // main: obs conversion (parallel with W_in conv), then GEMM1
    rowconv_kernel<<<(M_TOT * OBS_DIM / 4 + 255) / 256, 256>>>(obs, obsh, obsl, M_TOT * OBS_DIM);
    cudaStreamWaitEvent(0, eWin, 0);
    mma_gemm_bf3<8><<<dim3(D_IN / 128, M_TOT / 128), 256, SMEM_BF16>>>(
        obsh, obsl, Winh, Winl, b_in, X, Xh, M_TOT, D_IN, OBS_DIM);
    cudaEventRecord(eX, 0);

    const size_t hA = (size_t)M_HALF * D_IN;   // row offset into X/Xh/Y
    const size_t hB = (size_t)M_HALF * HN;     // row offset into Bm/Cm

    // B projection halves on main stream
    cudaStreamWaitEvent(0, eWB, 0);
    mma_gemm_h1<64><<<dim3(HN / 128, M_HALF / 128), 256, SMEM_F16_2>>>(
        Xh, WBh, Bmp, M_HALF, HN, D_IN);
    cudaEventRecord(eB1, 0);
    mma_gemm_h1<64><<<dim3(HN / 128, M_HALF / 128), 256, SMEM_F16_2>>>(
        Xh + hA, WBh, Bmp + hB, M_HALF, HN, D_IN);
    cudaEventRecord(eB2, 0);

    // C projection halves on stream B
    cudaStreamWaitEvent(sB, eX, 0);
    cudaStreamWaitEvent(sB, eWC, 0);
    mma_gemm_h1<64><<<dim3(HN / 128, M_HALF / 128), 256, SMEM_F16_2, sB>>>(
        Xh, WCh, Cmp, M_HALF, HN, D_IN);
    cudaEventRecord(eC1, sB);
    mma_gemm_h1<64><<<dim3(HN / 128, M_HALF / 128), 256, SMEM_F16_2, sB>>>(
        Xh + hA, WCh, Cmp + hB, M_HALF, HN, D_IN);
    cudaEventRecord(eC2, sB);

    // dt/decay (full) on stream C, then scan chunks on stream C
    cudaStreamWaitEvent(sC, eX, 0);
    dtdecay_kernel<<<M_TOT / 16, 256, 0, sC>>>(X, W_dt, dt_bias, A_log, dts, dec);

    cudaStreamWaitEvent(sC, eB1, 0);
    cudaStreamWaitEvent(sC, eC1, 0);
    scan_kernel<<<BSZ * NHEAD, 128, 0, sC>>>(X, Bmp, Cmp, dts, dec, Yhi, Ylo,
                                             hst, 0, T_LEN / 2, 1);
    cudaEventRecord(eS1, sC);
    cudaStreamWaitEvent(sC, eB2, 0);
    cudaStreamWaitEvent(sC, eC2, 0);
    scan_kernel<<<BSZ * NHEAD, 128, 0, sC>>>(X, Bmp, Cmp, dts, dec, Yhi, Ylo,
                                             hst, T_LEN / 2, T_LEN, 0);
    cudaEventRecord(eS2, sC);

    // yo projection halves (split-K=2) on main stream, overlapping scan2
    const size_t zstride = (size_t)M_TOT * NUNITS;
    cudaStreamWaitEvent(0, eWyo, 0);
    cudaStreamWaitEvent(0, eS1, 0);
    mma_gemm_h2<32><<<dim3(NUNITS / 128, M_HALF / 128, 2), 256, SMEM_F16_3>>>(
        Yhi, Ylo, Wyoh, Zp, M_HALF, NUNITS, D_IN, zstride);
    cudaStreamWaitEvent(0, eS2, 0);
    mma_gemm_h2<32><<<dim3(NUNITS / 128, M_HALF / 128, 2), 256, SMEM_F16_3>>>(
        Yhi + hA, Ylo + hA, Wyoh, Zp + (size_t)M_HALF * NUNITS, M_HALF, NUNITS, D_IN, zstride);

    head_kernel<<<M_TOT / 4, 256>>>(Zp, b_yo, W_head, b_head, out);
}